// round 11
// baseline (speedup 1.0000x reference)
#include <cuda_runtime.h>
#include <math.h>
#include <stdint.h>

#define Bz 2
#define Tt 1024
#define Dd 512
#define NHh 8
#define Ll 4
#define Ee 8
#define Hh 2048
#define NT (Bz*Tt)

#define SZ_QKV ((size_t)Ll*1536*Dd)
#define SZ_OUT ((size_t)Ll*Dd*Dd)
#define SZ_MW  ((size_t)2*Ee*Hh*Dd)
#define SZ_MW1 (SZ_MW/2)
#define SZ_FW  ((size_t)2*Hh*Dd)
#define OFF_QKV 0ull
#define OFF_OUT (OFF_QKV+SZ_QKV)
#define OFF_MW1 (OFF_OUT+SZ_OUT)
#define OFF_MW3 (OFF_MW1+SZ_MW)
#define OFF_MW2 (OFF_MW3+SZ_MW)
#define OFF_FW1 (OFF_MW2+SZ_MW)
#define OFF_FW3 (OFF_FW1+SZ_FW)
#define OFF_FW2 (OFF_FW3+SZ_FW)
#define WR_TOTAL (OFF_FW2+SZ_FW)

__device__ float g_h[NT*Dd];
__device__ float g_xn[NT*Dd];
__device__ float g_xn32[NT*Dd];
__device__ float g_qkv[NT*3*Dd];
__device__ float g_q[NT*Dd];
__device__ float g_k[NT*Dd];
__device__ float g_v[NT*Dd];
__device__ float g_attn[NT*Dd];
__device__ float g_hbuf[(size_t)Ee*NT*Hh];
__device__ float g_wr[WR_TOTAL];
__device__ int   g_cnt[Ee];
__device__ int   g_tok[Ee*NT];
__device__ float g_wt[Ee*NT];

// ---------------- helpers -----------------------------------------------------
__device__ __forceinline__ uint32_t s2u(const void* p){
    uint32_t a;
    asm("{ .reg .u64 t; cvta.to.shared.u64 t, %1; cvt.u32.u64 %0, t; }":"=r"(a):"l"(p));
    return a;
}
__device__ __forceinline__ float to_tf32(float x){
    uint32_t u; asm("cvt.rn.tf32.f32 %0, %1;":"=r"(u):"f"(x));
    return __uint_as_float(u);
}
__device__ __forceinline__ void cp16(uint32_t dst, const void* src){
    asm volatile("cp.async.cg.shared.global [%0], [%1], 16;"::"r"(dst),"l"(src));
}
#define CP_COMMIT() asm volatile("cp.async.commit_group;")
#define fau __float_as_uint

#define MMA8(d,a,b0,b1) \
  asm volatile("mma.sync.aligned.m16n8k8.row.col.f32.tf32.tf32.f32 " \
    "{%0,%1,%2,%3},{%4,%5,%6,%7},{%8,%9},{%0,%1,%2,%3};" \
    : "+f"((d)[0]),"+f"((d)[1]),"+f"((d)[2]),"+f"((d)[3]) \
    : "r"((a)[0]),"r"((a)[1]),"r"((a)[2]),"r"((a)[3]),"r"(b0),"r"(b1))

// ============ tf32 mma.sync GEMM v2: C = A @ B^T ==============================
// CTA: 64 threads (2 warps). CTA tile 64 rows x (FUSED?64:128) cols.
// Warp tile 64 x (FUSED? 32(dual) : 64). K-chunk 32, smem stride 36.
// MODE 0 store, 1 +=, 3 weighted atomic scatter-add into token rows.
template<bool FUSED, bool GROUPED, int MODE>
__global__ void __launch_bounds__(64) mm_kernel(
    const float* __restrict__ A, const float* __restrict__ B1, const float* __restrict__ B3,
    float* __restrict__ C, const int* __restrict__ cnt, const int* __restrict__ tok,
    const float* __restrict__ wtv, int K, int ldc, int nrows,
    long long sAe, long long sBe, long long sCe)
{
    constexpr int NCOLS = FUSED ? 64 : 128;
    constexpr int NJ    = FUSED ? 4  : 8;      // n-frags per warp (per acc set)
    constexpr int LDS   = 36;
    extern __shared__ float sm[];
    float* As = sm;                            // [2][64][36]
    float* Bs = sm + 2*64*LDS;                 // [2][128][36]

    int e = GROUPED ? blockIdx.z : 0;
    int n = GROUPED ? cnt[e] : nrows;
    int rb = blockIdx.y*64;
    if (rb >= n) return;
    int cb = blockIdx.x*NCOLS;
    if (GROUPED) {
        if (!FUSED) A += (size_t)e*sAe;
        B1 += (size_t)e*sBe;
        if (FUSED) B3 += (size_t)e*sBe;
        C += (size_t)e*sCe;
    }
    int t = threadIdx.x;
    int lane = t & 31, w = t >> 5;             // 2 warps: w = col half
    int tq = lane >> 2, tr = lane & 3;

    // gmem pointers: A 8 rows-of-16B, B 16 per thread per chunk
    const float* Ap[8]; const float* Bp[16];
#pragma unroll
    for (int i = 0; i < 8; i++) {
        int lin = t + i*64;
        int row = lin >> 3, kq = (lin & 7) << 2;
        int ar = rb + row; if (GROUPED && ar > n-1) ar = n-1;
        if (GROUPED && FUSED) Ap[i] = A + (size_t)(tok[(size_t)e*NT + ar] >> 1)*K + kq;
        else                  Ap[i] = A + (size_t)ar*K + kq;
    }
#pragma unroll
    for (int i = 0; i < 16; i++) {
        int lin = t + i*64;
        int row = lin >> 3, kq = (lin & 7) << 2;
        if (!FUSED) Bp[i] = B1 + (size_t)(cb + row)*K + kq;
        else {
            const float* bb = (row < 64) ? B1 : B3;
            Bp[i] = bb + (size_t)(cb + (row & 63))*K + kq;
        }
    }
    uint32_t sA = s2u(As), sB = s2u(Bs);

    float acc1[4][NJ][4];
    float acc3[FUSED?4:1][NJ][4];
#pragma unroll
    for (int i = 0; i < 4; i++)
#pragma unroll
        for (int j = 0; j < NJ; j++)
#pragma unroll
            for (int q = 0; q < 4; q++) { acc1[i][j][q] = 0.f; if (FUSED) acc3[i][j][q] = 0.f; }

    auto load = [&](int c, int s){
#pragma unroll
        for (int i = 0; i < 8; i++) {
            int lin = t + i*64;
            int row = lin >> 3, kq = (lin & 7) << 2;
            cp16(sA + (uint32_t)(((s*64 + row)*LDS + kq)*4), Ap[i] + (size_t)c*32);
        }
#pragma unroll
        for (int i = 0; i < 16; i++) {
            int lin = t + i*64;
            int row = lin >> 3, kq = (lin & 7) << 2;
            cp16(sB + (uint32_t)(((s*128 + row)*LDS + kq)*4), Bp[i] + (size_t)c*32);
        }
        CP_COMMIT();
    };

    const int NC = K >> 5;
    load(0, 0);
    for (int c = 0; c < NC; c++) {
        int s = c & 1;
        if (c+1 < NC) { load(c+1, s^1); asm volatile("cp.async.wait_group 1;"); }
        else asm volatile("cp.async.wait_group 0;");
        __syncthreads();
        const float* Ab = As + (size_t)s*64*LDS;
        const float* Bb = Bs + (size_t)s*128*LDS;
#pragma unroll
        for (int ks = 0; ks < 4; ks++) {
            int k0 = ks*8;
            uint32_t a[4][4];
#pragma unroll
            for (int i = 0; i < 4; i++) {
                int r0 = i*16;
                a[i][0] = fau(Ab[(r0+tq  )*LDS + k0+tr  ]);
                a[i][1] = fau(Ab[(r0+tq+8)*LDS + k0+tr  ]);
                a[i][2] = fau(Ab[(r0+tq  )*LDS + k0+tr+4]);
                a[i][3] = fau(Ab[(r0+tq+8)*LDS + k0+tr+4]);
            }
#pragma unroll
            for (int j = 0; j < NJ; j++) {
                int bc = w*(NJ*8) + j*8 + tq;
                uint32_t b0 = fau(Bb[bc*LDS + k0+tr]);
                uint32_t b1 = fau(Bb[bc*LDS + k0+tr+4]);
#pragma unroll
                for (int i = 0; i < 4; i++) MMA8(acc1[i][j], a[i], b0, b1);
                if (FUSED) {
                    uint32_t c0 = fau(Bb[(bc+64)*LDS + k0+tr]);
                    uint32_t c1 = fau(Bb[(bc+64)*LDS + k0+tr+4]);
#pragma unroll
                    for (int i = 0; i < 4; i++) MMA8(acc3[i][j], a[i], c0, c1);
                }
            }
        }
        __syncthreads();
    }

    // -------- epilogue --------
#pragma unroll
    for (int i = 0; i < 4; i++)
#pragma unroll
        for (int hh = 0; hh < 2; hh++) {
            int gr = rb + i*16 + tq + hh*8;
            if (GROUPED && gr >= n) continue;
            int orow = gr; float wv = 1.f;
            if (GROUPED && MODE == 3) {
                int pk = tok[(size_t)e*NT + gr];
                wv   = wtv[(size_t)e*NT + gr];
                orow = pk >> 1;
            }
            float* cr = C + (size_t)orow*ldc;
#pragma unroll
            for (int j = 0; j < NJ; j++) {
                int gc = cb + w*(NJ*8) + j*8 + tr*2;
                float v0 = acc1[i][j][hh*2], v1 = acc1[i][j][hh*2+1];
                if (FUSED) {
                    float u0 = acc3[i][j][hh*2], u1 = acc3[i][j][hh*2+1];
                    float2 o;
                    o.x = to_tf32(v0/(1.f+__expf(-v0))*u0);
                    o.y = to_tf32(v1/(1.f+__expf(-v1))*u1);
                    *(float2*)(cr + gc) = o;
                } else if (MODE == 0) {
                    float2 o = {v0, v1};
                    *(float2*)(cr + gc) = o;
                } else if (MODE == 1) {
                    float2 o = *(float2*)(cr + gc);
                    o.x += v0; o.y += v1;
                    *(float2*)(cr + gc) = o;
                } else {
                    atomicAdd(cr + gc,     wv*v0);
                    atomicAdd(cr + gc + 1, wv*v1);
                }
            }
        }
}

// ---------------- weight rounding fp32 -> RN tf32 ----------------------------
__global__ void round_copy(const float* __restrict__ s, float* __restrict__ d, int n4){
    int i = blockIdx.x*256 + threadIdx.x;
    if (i >= n4) return;
    float4 v = ((const float4*)s)[i];
    v.x=to_tf32(v.x); v.y=to_tf32(v.y); v.z=to_tf32(v.z); v.w=to_tf32(v.w);
    ((float4*)d)[i] = v;
}

// ---------------- rmsnorm ------------------------------------------------------
template<bool ROUND>
__global__ void rmsnorm_kernel(const float* __restrict__ in, const float* __restrict__ w,
                               float* __restrict__ out, float* __restrict__ out32){
    int row = blockIdx.x;
    const float* x = in + (size_t)row*Dd;
    float s = 0.f;
    for (int j = threadIdx.x; j < Dd; j += 256) { float v = x[j]; s += v*v; }
    __shared__ float red[8];
    for (int o = 16; o; o >>= 1) s += __shfl_xor_sync(0xffffffffu, s, o);
    if ((threadIdx.x & 31) == 0) red[threadIdx.x>>5] = s;
    __syncthreads();
    if (threadIdx.x < 8) {
        float v = red[threadIdx.x];
        for (int o = 4; o; o >>= 1) v += __shfl_xor_sync(0xffu, v, o);
        if (threadIdx.x == 0) red[0] = v;
    }
    __syncthreads();
    float rms = rsqrtf(red[0]/(float)Dd + 1e-5f);
    for (int j = threadIdx.x; j < Dd; j += 256) {
        float v = w[j]*x[j]*rms;
        out[(size_t)row*Dd+j] = ROUND ? to_tf32(v) : v;
        if (out32) out32[(size_t)row*Dd+j] = v;
    }
}

// ---------------- qkv split + RoPE (RN-tf32 outputs, Q pre-scaled) ------------
__global__ void split_rope_kernel(const float* __restrict__ qkv, float* __restrict__ Q,
                                  float* __restrict__ K, float* __restrict__ V){
    int idx = blockIdx.x*256 + threadIdx.x;
    if (idx >= NT*NHh*32) return;
    int d = idx & 31, h = (idx>>5)&7, bt = idx>>8;
    int tt = bt & (Tt-1), b = bt>>10;
    float inv = expf(-(float)d*0.28782313662425575f);
    float sn, cs; sincosf((float)tt*inv, &sn, &cs);
    size_t bi = (size_t)bt*1536 + h*64 + d;
    float q1=qkv[bi], q2=qkv[bi+32], k1=qkv[bi+512], k2=qkv[bi+544], v1=qkv[bi+1024], v2=qkv[bi+1056];
    size_t oi = ((size_t)(b*NHh+h)*Tt + tt)*64 + d;
    Q[oi]   =to_tf32((q1*cs-q2*sn)*0.125f); Q[oi+32]=to_tf32((q1*sn+q2*cs)*0.125f);
    K[oi]   =to_tf32(k1*cs-k2*sn);          K[oi+32]=to_tf32(k1*sn+k2*cs);
    V[oi]   =to_tf32(v1);                   V[oi+32]=to_tf32(v2);
}

// ---------------- tensor-core flash attention (causal, HD=64) -----------------
#define LDP 72
__global__ void __launch_bounds__(128) attn_tc_kernel(
    const float* __restrict__ Q, const float* __restrict__ K,
    const float* __restrict__ V, float* __restrict__ Out)
{
    extern __shared__ float sm[];
    float* Ks = sm;
    float* Vs = sm + 2*64*LDP;
    float* Ps = sm + 4*64*LDP;
    int bh = blockIdx.y;
    int t = threadIdx.x, lane = t & 31, w = t >> 5;
    int tq = lane >> 2, tr = lane & 3;
    const float* Qb = Q + (size_t)bh*Tt*64;
    const float* Kb = K + (size_t)bh*Tt*64;
    const float* Vb = V + (size_t)bh*Tt*64;
    int b = bh >> 3, hh = bh & 7;
    uint32_t sK = s2u(Ks), sV = s2u(Vs);

    auto load_kv = [&](int kt, int buf){
        const float* ks = Kb + (size_t)kt*64*64;
        const float* vs = Vb + (size_t)kt*64*64;
        uint32_t kd = sK + buf*64*LDP*4;
        uint32_t vd = sV + buf*64*LDP*4;
#pragma unroll
        for (int i = 0; i < 8; i++) {
            int u = t + i*128;
            int row = u >> 4, seg = u & 15;
            uint32_t off = (uint32_t)((row*LDP + seg*4)*4);
            cp16(kd + off, ks + row*64 + seg*4);
            cp16(vd + off, vs + row*64 + seg*4);
        }
        CP_COMMIT();
    };

    for (int pass = 0; pass < 2; pass++) {
        int qt = pass ? (15 - (int)blockIdx.x) : (int)blockIdx.x;
        int nkt = qt + 1;
        __syncthreads();
        load_kv(0, 0);
        for (int u = t; u < 64*16; u += 128) {
            int row = u >> 4, seg = u & 15;
            *(float4*)&Ps[row*LDP + seg*4] = *(const float4*)(Qb + (size_t)(qt*64+row)*64 + seg*4);
        }
        __syncthreads();
        uint32_t qa[8][4];
        int r0 = w*16 + tq;
#pragma unroll
        for (int ks = 0; ks < 8; ks++) {
            qa[ks][0] = fau(Ps[ r0   *LDP + ks*8+tr  ]);
            qa[ks][1] = fau(Ps[(r0+8)*LDP + ks*8+tr  ]);
            qa[ks][2] = fau(Ps[ r0   *LDP + ks*8+tr+4]);
            qa[ks][3] = fau(Ps[(r0+8)*LDP + ks*8+tr+4]);
        }
        float o[8][4];
#pragma unroll
        for (int j = 0; j < 8; j++)
#pragma unroll
            for (int q = 0; q < 4; q++) o[j][q] = 0.f;
        float m0 = -1e30f, m1 = -1e30f, l0 = 0.f, l1 = 0.f;

        for (int kt = 0; kt < nkt; kt++) {
            int buf = kt & 1;
            __syncthreads();
            if (kt+1 < nkt) { load_kv(kt+1, buf^1); asm volatile("cp.async.wait_group 1;"); }
            else asm volatile("cp.async.wait_group 0;");
            __syncthreads();

            const float* Kt = Ks + buf*64*LDP;
            const float* Vt = Vs + buf*64*LDP;
            float s[8][4];
#pragma unroll
            for (int j = 0; j < 8; j++)
#pragma unroll
                for (int q = 0; q < 4; q++) s[j][q] = 0.f;
#pragma unroll
            for (int nf = 0; nf < 8; nf++) {
#pragma unroll
                for (int ks = 0; ks < 8; ks++) {
                    uint32_t b0 = fau(Kt[(nf*8+tq)*LDP + ks*8+tr  ]);
                    uint32_t b1 = fau(Kt[(nf*8+tq)*LDP + ks*8+tr+4]);
                    MMA8(s[nf], qa[ks], b0, b1);
                }
            }
            if (kt == qt) {
                int qr0 = qt*64 + r0, qr1 = qr0 + 8;
#pragma unroll
                for (int nf = 0; nf < 8; nf++) {
                    int kc = kt*64 + nf*8 + 2*tr;
                    if (kc   > qr0) s[nf][0] = -1e30f;
                    if (kc+1 > qr0) s[nf][1] = -1e30f;
                    if (kc   > qr1) s[nf][2] = -1e30f;
                    if (kc+1 > qr1) s[nf][3] = -1e30f;
                }
            }
            float rm0 = -1e30f, rm1 = -1e30f;
#pragma unroll
            for (int nf = 0; nf < 8; nf++) {
                rm0 = fmaxf(rm0, fmaxf(s[nf][0], s[nf][1]));
                rm1 = fmaxf(rm1, fmaxf(s[nf][2], s[nf][3]));
            }
            rm0 = fmaxf(rm0, __shfl_xor_sync(0xffffffffu, rm0, 1));
            rm0 = fmaxf(rm0, __shfl_xor_sync(0xffffffffu, rm0, 2));
            rm1 = fmaxf(rm1, __shfl_xor_sync(0xffffffffu, rm1, 1));
            rm1 = fmaxf(rm1, __shfl_xor_sync(0xffffffffu, rm1, 2));
            float nm0 = fmaxf(m0, rm0), nm1 = fmaxf(m1, rm1);
            float f0 = __expf(m0 - nm0), f1 = __expf(m1 - nm1);
            float rs0 = 0.f, rs1 = 0.f;
#pragma unroll
            for (int nf = 0; nf < 8; nf++) {
                float p0 = __expf(s[nf][0] - nm0);
                float p1 = __expf(s[nf][1] - nm0);
                float p2 = __expf(s[nf][2] - nm1);
                float p3 = __expf(s[nf][3] - nm1);
                rs0 += p0 + p1; rs1 += p2 + p3;
                Ps[ r0   *LDP + nf*8 + 2*tr    ] = to_tf32(p0);
                Ps[ r0   *LDP + nf*8 + 2*tr + 1] = to_tf32(p1);
                Ps[(r0+8)*LDP + nf*8 + 2*tr    ] = to_tf32(p2);
                Ps[(r0+8)*LDP + nf*8 + 2*tr + 1] = to_tf32(p3);
            }
            rs0 += __shfl_xor_sync(0xffffffffu, rs0, 1);
            rs0 += __shfl_xor_sync(0xffffffffu, rs0, 2);
            rs1 += __shfl_xor_sync(0xffffffffu, rs1, 1);
            rs1 += __shfl_xor_sync(0xffffffffu, rs1, 2);
            l0 = l0*f0 + rs0; m0 = nm0;
            l1 = l1*f1 + rs1; m1 = nm1;
#pragma unroll
            for (int j = 0; j < 8; j++) { o[j][0]*=f0; o[j][1]*=f0; o[j][2]*=f1; o[j][3]*=f1; }
            __syncwarp();
            uint32_t pa[8][4];
#pragma unroll
            for (int ks = 0; ks < 8; ks++) {
                pa[ks][0] = fau(Ps[ r0   *LDP + ks*8+tr  ]);
                pa[ks][1] = fau(Ps[(r0+8)*LDP + ks*8+tr  ]);
                pa[ks][2] = fau(Ps[ r0   *LDP + ks*8+tr+4]);
                pa[ks][3] = fau(Ps[(r0+8)*LDP + ks*8+tr+4]);
            }
#pragma unroll
            for (int nf = 0; nf < 8; nf++) {
#pragma unroll
                for (int ks = 0; ks < 8; ks++) {
                    uint32_t b0 = fau(Vt[(ks*8+tr  )*LDP + nf*8+tq]);
                    uint32_t b1 = fau(Vt[(ks*8+tr+4)*LDP + nf*8+tq]);
                    MMA8(o[nf], pa[ks], b0, b1);
                }
            }
        }
        float il0 = 1.f/l0, il1 = 1.f/l1;
        int qr = qt*64 + r0;
        float* o0 = Out + ((size_t)(b*Tt + qr    ))*Dd + hh*64;
        float* o1 = Out + ((size_t)(b*Tt + qr + 8))*Dd + hh*64;
#pragma unroll
        for (int nf = 0; nf < 8; nf++) {
            int gc = nf*8 + 2*tr;
            float2 a = { to_tf32(o[nf][0]*il0), to_tf32(o[nf][1]*il0) };
            float2 c = { to_tf32(o[nf][2]*il1), to_tf32(o[nf][3]*il1) };
            *(float2*)(o0 + gc) = a;
            *(float2*)(o1 + gc) = c;
        }
    }
}

// ---------------- router (fp32, unrounded input) ------------------------------
__global__ void router_kernel(const float* __restrict__ X, const float* __restrict__ RW,
                              int* __restrict__ cnt, int* __restrict__ tok, float* __restrict__ wt){
    int g = blockIdx.x*blockDim.x + threadIdx.x;
    int warp = g>>5, lane = g&31;
    if (warp >= NT) return;
    const float* xr = X + (size_t)warp*Dd;
    float lg[Ee];
#pragma unroll
    for (int e = 0; e < Ee; e++) {
        const float* w = RW + (size_t)e*Dd;
        float s = 0.f;
        for (int j = lane; j < Dd; j += 32) s += xr[j]*w[j];
        for (int o = 16; o; o >>= 1) s += __shfl_xor_sync(0xffffffffu, s, o);
        lg[e] = s;
    }
    if (lane == 0) {
        int i0 = 0; float v0 = lg[0];
#pragma unroll
        for (int e = 1; e < Ee; e++) if (lg[e] > v0) { v0 = lg[e]; i0 = e; }
        int i1 = -1; float v1 = -3.4e38f;
#pragma unroll
        for (int e = 0; e < Ee; e++) if (e != i0 && lg[e] > v1) { v1 = lg[e]; i1 = e; }
        float e1 = expf(v1 - v0);
        float w0 = 1.f/(1.f+e1), w1 = e1/(1.f+e1);
        int p0 = atomicAdd(&cnt[i0], 1);
        tok[i0*NT+p0] = warp*2;   wt[i0*NT+p0] = w0;
        int p1 = atomicAdd(&cnt[i1], 1);
        tok[i1*NT+p1] = warp*2+1; wt[i1*NT+p1] = w1;
    }
}

// ---------------- host orchestration ------------------------------------------
extern "C" void kernel_launch(void* const* d_in, const int* in_sizes, int n_in,
                              void* d_out, int out_size) {
    (void)in_sizes; (void)n_in; (void)out_size;
    const float* x        = (const float*)d_in[0];
    const float* qkv_w    = (const float*)d_in[1];
    const float* out_w    = (const float*)d_in[2];
    const float* norm1_w  = (const float*)d_in[3];
    const float* norm2_w  = (const float*)d_in[4];
    const float* router_w = (const float*)d_in[5];
    const float* moe_w1   = (const float*)d_in[6];
    const float* moe_w2   = (const float*)d_in[7];
    const float* moe_w3   = (const float*)d_in[8];
    const float* f_w1     = (const float*)d_in[9];
    const float* f_w2     = (const float*)d_in[10];
    const float* f_w3     = (const float*)d_in[11];
    const float* norm_f   = (const float*)d_in[12];
    float* out = (float*)d_out;

    float *h,*xn,*xn32,*qkv,*q,*k,*v,*attn,*hbuf,*wt,*wr;
    int *cnt,*tok;
    cudaGetSymbolAddress((void**)&h, g_h);       cudaGetSymbolAddress((void**)&xn, g_xn);
    cudaGetSymbolAddress((void**)&xn32, g_xn32); cudaGetSymbolAddress((void**)&qkv, g_qkv);
    cudaGetSymbolAddress((void**)&q, g_q);       cudaGetSymbolAddress((void**)&k, g_k);
    cudaGetSymbolAddress((void**)&v, g_v);       cudaGetSymbolAddress((void**)&attn, g_attn);
    cudaGetSymbolAddress((void**)&hbuf, g_hbuf);
    cudaGetSymbolAddress((void**)&wr, g_wr);     cudaGetSymbolAddress((void**)&cnt, g_cnt);
    cudaGetSymbolAddress((void**)&tok, g_tok);   cudaGetSymbolAddress((void**)&wt, g_wt);

    static cudaStream_t s1 = nullptr;
    static cudaEvent_t evF = nullptr, evJ0 = nullptr, evJ1 = nullptr, evJ2 = nullptr;
    if (!s1) {
        cudaStreamCreateWithFlags(&s1, cudaStreamNonBlocking);
        cudaEventCreateWithFlags(&evF,  cudaEventDisableTiming);
        cudaEventCreateWithFlags(&evJ0, cudaEventDisableTiming);
        cudaEventCreateWithFlags(&evJ1, cudaEventDisableTiming);
        cudaEventCreateWithFlags(&evJ2, cudaEventDisableTiming);
    }

    const int attn_smem = 5*64*LDP*sizeof(float);
    cudaFuncSetAttribute(attn_tc_kernel, cudaFuncAttributeMaxDynamicSharedMemorySize, attn_smem);
    const int SM2 = (2*64*36 + 2*128*36)*4;     // 55,296 B
    cudaFuncSetAttribute(mm_kernel<false,false,0>, cudaFuncAttributeMaxDynamicSharedMemorySize, SM2);
    cudaFuncSetAttribute(mm_kernel<false,false,1>, cudaFuncAttributeMaxDynamicSharedMemorySize, SM2);
    cudaFuncSetAttribute(mm_kernel<false,true ,3>, cudaFuncAttributeMaxDynamicSharedMemorySize, SM2);
    cudaFuncSetAttribute(mm_kernel<true ,false,0>, cudaFuncAttributeMaxDynamicSharedMemorySize, SM2);
    cudaFuncSetAttribute(mm_kernel<true ,true ,0>, cudaFuncAttributeMaxDynamicSharedMemorySize, SM2);

    // ---- fork: big weight rounding on s1 -------------------------------------
    cudaEventRecord(evF, 0);
    cudaStreamWaitEvent(s1, evF, 0);
    #define RC(st, src, dstoff, nfl) \
        round_copy<<<(int)(((nfl)/4+255)/256),256,0,st>>>((src), wr+(dstoff), (int)((nfl)/4))
    RC(s1, moe_w1,            OFF_MW1,        SZ_MW1);
    RC(s1, moe_w3,            OFF_MW3,        SZ_MW1);
    RC(s1, moe_w2,            OFF_MW2,        SZ_MW1);
    cudaEventRecord(evJ0, s1);
    RC(s1, f_w1, OFF_FW1, SZ_FW);
    RC(s1, f_w3, OFF_FW3, SZ_FW);
    RC(s1, f_w2, OFF_FW2, SZ_FW);
    cudaEventRecord(evJ1, s1);
    RC(s1, moe_w1+SZ_MW1,     OFF_MW1+SZ_MW1, SZ_MW1);
    RC(s1, moe_w3+SZ_MW1,     OFF_MW3+SZ_MW1, SZ_MW1);
    RC(s1, moe_w2+SZ_MW1,     OFF_MW2+SZ_MW1, SZ_MW1);
    cudaEventRecord(evJ2, s1);

    // ---- main stream ---------------------------------------------------------
    RC((cudaStream_t)0, qkv_w, OFF_QKV, SZ_QKV);
    RC((cudaStream_t)0, out_w, OFF_OUT, SZ_OUT);
    cudaMemcpyAsync(h, x, (size_t)NT*Dd*sizeof(float), cudaMemcpyDeviceToDevice, 0);

    for (int l = 0; l < Ll; l++) {
        rmsnorm_kernel<true><<<NT,256>>>(h, norm1_w+(size_t)l*Dd, xn, nullptr);
        mm_kernel<false,false,0><<<dim3(12,32),64,SM2>>>(
            xn, wr+OFF_QKV+(size_t)l*1536*Dd, nullptr, qkv,
            nullptr,nullptr,nullptr, Dd, 1536, NT, 0,0,0);
        split_rope_kernel<<<(NT*NHh*32+255)/256,256>>>(qkv, q, k, v);
        attn_tc_kernel<<<dim3(8, Bz*NHh),128,attn_smem>>>(q, k, v, attn);
        mm_kernel<false,false,1><<<dim3(4,32),64,SM2>>>(
            attn, wr+OFF_OUT+(size_t)l*Dd*Dd, nullptr, h,
            nullptr,nullptr,nullptr, Dd, Dd, NT, 0,0,0);

        if (l == 0 || l == 2) {
            int m = l/2;
            rmsnorm_kernel<true><<<NT,256>>>(h, norm2_w+(size_t)l*Dd, xn, xn32);
            cudaMemsetAsync(cnt, 0, Ee*sizeof(int), 0);
            router_kernel<<<(NT*32+127)/128,128>>>(xn32, router_w+(size_t)m*Ee*Dd, cnt, tok, wt);
            cudaStreamWaitEvent((cudaStream_t)0, m == 0 ? evJ0 : evJ2, 0);
            mm_kernel<true,true,0><<<dim3(Hh/64,32,Ee),64,SM2>>>(
                xn, wr+OFF_MW1+(size_t)m*SZ_MW1, wr+OFF_MW3+(size_t)m*SZ_MW1, hbuf,
                cnt, tok, nullptr, Dd, Hh, 0, 0, (long long)Hh*Dd, (long long)NT*Hh);
            mm_kernel<false,true,3><<<dim3(4,32,Ee),64,SM2>>>(
                hbuf, wr+OFF_MW2+(size_t)m*SZ_MW1, nullptr, h,
                cnt, tok, wt, Hh, Dd, 0, (long long)NT*Hh, (long long)Dd*Hh, 0);
        } else {
            int m = (l == 1) ? 0 : 1;
            rmsnorm_kernel<true><<<NT,256>>>(h, norm2_w+(size_t)l*Dd, xn, nullptr);
            if (l == 1) cudaStreamWaitEvent((cudaStream_t)0, evJ1, 0);
            mm_kernel<true,false,0><<<dim3(Hh/64,32),64,SM2>>>(
                xn, wr+OFF_FW1+(size_t)m*Hh*Dd, wr+OFF_FW3+(size_t)m*Hh*Dd, hbuf,
                nullptr,nullptr,nullptr, Dd, Hh, NT, 0,0,0);
            mm_kernel<false,false,1><<<dim3(4,32),64,SM2>>>(
                hbuf, wr+OFF_FW2+(size_t)m*Dd*Hh, nullptr, h,
                nullptr,nullptr,nullptr, Hh, Dd, NT, 0,0,0);
        }
    }
    rmsnorm_kernel<false><<<NT,256>>>(h, norm_f, out, nullptr);
}

// round 12
// speedup vs baseline: 1.0373x; 1.0373x over previous
#include <cuda_runtime.h>
#include <math.h>
#include <stdint.h>

#define Bz 2
#define Tt 1024
#define Dd 512
#define NHh 8
#define Ll 4
#define Ee 8
#define Hh 2048
#define NT (Bz*Tt)

#define SZ_QKV ((size_t)Ll*1536*Dd)
#define SZ_OUT ((size_t)Ll*Dd*Dd)
#define SZ_MW  ((size_t)2*Ee*Hh*Dd)
#define SZ_MW1 (SZ_MW/2)
#define SZ_FW  ((size_t)2*Hh*Dd)
#define OFF_QKV 0ull
#define OFF_OUT (OFF_QKV+SZ_QKV)
#define OFF_MW1 (OFF_OUT+SZ_OUT)
#define OFF_MW3 (OFF_MW1+SZ_MW)
#define OFF_MW2 (OFF_MW3+SZ_MW)
#define OFF_FW1 (OFF_MW2+SZ_MW)
#define OFF_FW3 (OFF_FW1+SZ_FW)
#define OFF_FW2 (OFF_FW3+SZ_FW)
#define WR_TOTAL (OFF_FW2+SZ_FW)

__device__ float g_h[NT*Dd];
__device__ float g_xn[NT*Dd];
__device__ float g_xn32[NT*Dd];
__device__ float g_qkv[NT*3*Dd];
__device__ float g_q[NT*Dd];
__device__ float g_k[NT*Dd];
__device__ float g_v[NT*Dd];
__device__ float g_attn[NT*Dd];
__device__ float g_hbuf[(size_t)Ee*NT*Hh];
__device__ float g_wr[WR_TOTAL];
__device__ int   g_cnt[Ee];
__device__ int   g_tok[Ee*NT];
__device__ float g_wt[Ee*NT];

// ---------------- helpers -----------------------------------------------------
__device__ __forceinline__ uint32_t s2u(const void* p){
    uint32_t a;
    asm("{ .reg .u64 t; cvta.to.shared.u64 t, %1; cvt.u32.u64 %0, t; }":"=r"(a):"l"(p));
    return a;
}
__device__ __forceinline__ float to_tf32(float x){
    uint32_t u; asm("cvt.rn.tf32.f32 %0, %1;":"=r"(u):"f"(x));
    return __uint_as_float(u);
}
__device__ __forceinline__ void cp16(uint32_t dst, const void* src){
    asm volatile("cp.async.cg.shared.global [%0], [%1], 16;"::"r"(dst),"l"(src));
}
#define CP_COMMIT() asm volatile("cp.async.commit_group;")
#define fau __float_as_uint

#define MMA8(d,a,b0,b1) \
  asm volatile("mma.sync.aligned.m16n8k8.row.col.f32.tf32.tf32.f32 " \
    "{%0,%1,%2,%3},{%4,%5,%6,%7},{%8,%9},{%0,%1,%2,%3};" \
    : "+f"((d)[0]),"+f"((d)[1]),"+f"((d)[2]),"+f"((d)[3]) \
    : "r"((a)[0]),"r"((a)[1]),"r"((a)[2]),"r"((a)[3]),"r"(b0),"r"(b1))

// ============ tf32 mma.sync GEMM v3: C = A @ B^T ==============================
// CTA: 128 threads (4 warps, 2x2). CTA tile 64 rows x (FUSED?64:128) cols.
// Warp tile 32 x 64 (non-fused) / 32 x 32 dual (fused). K-chunk 32, stride 36.
// MODE 0 store, 1 +=, 3 weighted atomic scatter-add into token rows.
template<bool FUSED, bool GROUPED, int MODE>
__global__ void __launch_bounds__(128) mm_kernel(
    const float* __restrict__ A, const float* __restrict__ B1, const float* __restrict__ B3,
    float* __restrict__ C, const int* __restrict__ cnt, const int* __restrict__ tok,
    const float* __restrict__ wtv, int K, int ldc, int nrows,
    long long sAe, long long sBe, long long sCe)
{
    constexpr int NCOLS = FUSED ? 64 : 128;
    constexpr int NJ    = NCOLS/16;            // n-frags per warp (8 or 4)
    constexpr int LDS   = 36;
    extern __shared__ float sm[];
    float* As = sm;                            // [2][64][36]
    float* Bs = sm + 2*64*LDS;                 // [2][128][36]

    int e = GROUPED ? blockIdx.z : 0;
    int n = GROUPED ? cnt[e] : nrows;
    int rb = blockIdx.y*64;
    if (rb >= n) return;
    int cb = blockIdx.x*NCOLS;
    if (GROUPED) {
        if (!FUSED) A += (size_t)e*sAe;
        B1 += (size_t)e*sBe;
        if (FUSED) B3 += (size_t)e*sBe;
        C += (size_t)e*sCe;
    }
    int t = threadIdx.x;
    int lane = t & 31, w = t >> 5;
    int wr = w >> 1, wc = w & 1;               // 2x2 warp grid
    int tq = lane >> 2, tr = lane & 3;

    // gmem pointers: A 4 x 16B, B 8 x 16B per thread per chunk
    const float* Ap[4]; const float* Bp[8];
#pragma unroll
    for (int i = 0; i < 4; i++) {
        int lin = t + i*128;
        int row = lin >> 3, kq = (lin & 7) << 2;
        int ar = rb + row; if (GROUPED && ar > n-1) ar = n-1;
        if (GROUPED && FUSED) Ap[i] = A + (size_t)(tok[(size_t)e*NT + ar] >> 1)*K + kq;
        else                  Ap[i] = A + (size_t)ar*K + kq;
    }
#pragma unroll
    for (int i = 0; i < 8; i++) {
        int lin = t + i*128;
        int row = lin >> 3, kq = (lin & 7) << 2;
        if (!FUSED) Bp[i] = B1 + (size_t)(cb + row)*K + kq;
        else {
            const float* bb = (row < 64) ? B1 : B3;
            Bp[i] = bb + (size_t)(cb + (row & 63))*K + kq;
        }
    }
    uint32_t sA = s2u(As), sB = s2u(Bs);

    float acc1[2][NJ][4];
    float acc3[FUSED?2:1][NJ][4];
#pragma unroll
    for (int i = 0; i < 2; i++)
#pragma unroll
        for (int j = 0; j < NJ; j++)
#pragma unroll
            for (int q = 0; q < 4; q++) { acc1[i][j][q] = 0.f; if (FUSED) acc3[i][j][q] = 0.f; }

    auto load = [&](int c, int s){
#pragma unroll
        for (int i = 0; i < 4; i++) {
            int lin = t + i*128;
            int row = lin >> 3, kq = (lin & 7) << 2;
            cp16(sA + (uint32_t)(((s*64 + row)*LDS + kq)*4), Ap[i] + (size_t)c*32);
        }
#pragma unroll
        for (int i = 0; i < 8; i++) {
            int lin = t + i*128;
            int row = lin >> 3, kq = (lin & 7) << 2;
            cp16(sB + (uint32_t)(((s*128 + row)*LDS + kq)*4), Bp[i] + (size_t)c*32);
        }
        CP_COMMIT();
    };

    const int NC = K >> 5;
    load(0, 0);
    for (int c = 0; c < NC; c++) {
        int s = c & 1;
        if (c+1 < NC) { load(c+1, s^1); asm volatile("cp.async.wait_group 1;"); }
        else asm volatile("cp.async.wait_group 0;");
        __syncthreads();
        const float* Ab = As + (size_t)s*64*LDS;
        const float* Bb = Bs + (size_t)s*128*LDS;
#pragma unroll
        for (int ks = 0; ks < 4; ks++) {
            int k0 = ks*8;
            uint32_t a[2][4];
#pragma unroll
            for (int i = 0; i < 2; i++) {
                int r0 = wr*32 + i*16;
                a[i][0] = fau(Ab[(r0+tq  )*LDS + k0+tr  ]);
                a[i][1] = fau(Ab[(r0+tq+8)*LDS + k0+tr  ]);
                a[i][2] = fau(Ab[(r0+tq  )*LDS + k0+tr+4]);
                a[i][3] = fau(Ab[(r0+tq+8)*LDS + k0+tr+4]);
            }
#pragma unroll
            for (int j = 0; j < NJ; j++) {
                int bc = wc*(NJ*8) + j*8 + tq;
                uint32_t b0 = fau(Bb[bc*LDS + k0+tr]);
                uint32_t b1 = fau(Bb[bc*LDS + k0+tr+4]);
#pragma unroll
                for (int i = 0; i < 2; i++) MMA8(acc1[i][j], a[i], b0, b1);
                if (FUSED) {
                    uint32_t c0 = fau(Bb[(bc+64)*LDS + k0+tr]);
                    uint32_t c1 = fau(Bb[(bc+64)*LDS + k0+tr+4]);
#pragma unroll
                    for (int i = 0; i < 2; i++) MMA8(acc3[i][j], a[i], c0, c1);
                }
            }
        }
        __syncthreads();
    }

    // -------- epilogue --------
#pragma unroll
    for (int i = 0; i < 2; i++)
#pragma unroll
        for (int hh = 0; hh < 2; hh++) {
            int gr = rb + wr*32 + i*16 + tq + hh*8;
            if (GROUPED && gr >= n) continue;
            int orow = gr; float wv = 1.f;
            if (GROUPED && MODE == 3) {
                int pk = tok[(size_t)e*NT + gr];
                wv   = wtv[(size_t)e*NT + gr];
                orow = pk >> 1;
            }
            float* cr = C + (size_t)orow*ldc;
#pragma unroll
            for (int j = 0; j < NJ; j++) {
                int gc = cb + wc*(NJ*8) + j*8 + tr*2;
                float v0 = acc1[i][j][hh*2], v1 = acc1[i][j][hh*2+1];
                if (FUSED) {
                    float u0 = acc3[i][j][hh*2], u1 = acc3[i][j][hh*2+1];
                    float2 o;
                    o.x = to_tf32(v0/(1.f+__expf(-v0))*u0);
                    o.y = to_tf32(v1/(1.f+__expf(-v1))*u1);
                    *(float2*)(cr + gc) = o;
                } else if (MODE == 0) {
                    float2 o = {v0, v1};
                    *(float2*)(cr + gc) = o;
                } else if (MODE == 1) {
                    float2 o = *(float2*)(cr + gc);
                    o.x += v0; o.y += v1;
                    *(float2*)(cr + gc) = o;
                } else {
                    atomicAdd(cr + gc,     wv*v0);
                    atomicAdd(cr + gc + 1, wv*v1);
                }
            }
        }
}

// ---------------- weight rounding fp32 -> RN tf32 ----------------------------
__global__ void round_copy(const float* __restrict__ s, float* __restrict__ d, int n4){
    int i = blockIdx.x*256 + threadIdx.x;
    if (i >= n4) return;
    float4 v = ((const float4*)s)[i];
    v.x=to_tf32(v.x); v.y=to_tf32(v.y); v.z=to_tf32(v.z); v.w=to_tf32(v.w);
    ((float4*)d)[i] = v;
}

// ---------------- rmsnorm ------------------------------------------------------
template<bool ROUND>
__global__ void rmsnorm_kernel(const float* __restrict__ in, const float* __restrict__ w,
                               float* __restrict__ out, float* __restrict__ out32){
    int row = blockIdx.x;
    const float* x = in + (size_t)row*Dd;
    float s = 0.f;
    for (int j = threadIdx.x; j < Dd; j += 256) { float v = x[j]; s += v*v; }
    __shared__ float red[8];
    for (int o = 16; o; o >>= 1) s += __shfl_xor_sync(0xffffffffu, s, o);
    if ((threadIdx.x & 31) == 0) red[threadIdx.x>>5] = s;
    __syncthreads();
    if (threadIdx.x < 8) {
        float v = red[threadIdx.x];
        for (int o = 4; o; o >>= 1) v += __shfl_xor_sync(0xffu, v, o);
        if (threadIdx.x == 0) red[0] = v;
    }
    __syncthreads();
    float rms = rsqrtf(red[0]/(float)Dd + 1e-5f);
    for (int j = threadIdx.x; j < Dd; j += 256) {
        float v = w[j]*x[j]*rms;
        out[(size_t)row*Dd+j] = ROUND ? to_tf32(v) : v;
        if (out32) out32[(size_t)row*Dd+j] = v;
    }
}

// ---------------- qkv split + RoPE (RN-tf32 outputs, Q pre-scaled) ------------
__global__ void split_rope_kernel(const float* __restrict__ qkv, float* __restrict__ Q,
                                  float* __restrict__ K, float* __restrict__ V){
    int idx = blockIdx.x*256 + threadIdx.x;
    if (idx >= NT*NHh*32) return;
    int d = idx & 31, h = (idx>>5)&7, bt = idx>>8;
    int tt = bt & (Tt-1), b = bt>>10;
    float inv = expf(-(float)d*0.28782313662425575f);
    float sn, cs; sincosf((float)tt*inv, &sn, &cs);
    size_t bi = (size_t)bt*1536 + h*64 + d;
    float q1=qkv[bi], q2=qkv[bi+32], k1=qkv[bi+512], k2=qkv[bi+544], v1=qkv[bi+1024], v2=qkv[bi+1056];
    size_t oi = ((size_t)(b*NHh+h)*Tt + tt)*64 + d;
    Q[oi]   =to_tf32((q1*cs-q2*sn)*0.125f); Q[oi+32]=to_tf32((q1*sn+q2*cs)*0.125f);
    K[oi]   =to_tf32(k1*cs-k2*sn);          K[oi+32]=to_tf32(k1*sn+k2*cs);
    V[oi]   =to_tf32(v1);                   V[oi+32]=to_tf32(v2);
}

// ---------------- tensor-core flash attention (causal, HD=64) -----------------
#define LDP 72
__global__ void __launch_bounds__(128) attn_tc_kernel(
    const float* __restrict__ Q, const float* __restrict__ K,
    const float* __restrict__ V, float* __restrict__ Out)
{
    extern __shared__ float sm[];
    float* Ks = sm;
    float* Vs = sm + 2*64*LDP;
    float* Ps = sm + 4*64*LDP;
    int bh = blockIdx.y;
    int t = threadIdx.x, lane = t & 31, w = t >> 5;
    int tq = lane >> 2, tr = lane & 3;
    const float* Qb = Q + (size_t)bh*Tt*64;
    const float* Kb = K + (size_t)bh*Tt*64;
    const float* Vb = V + (size_t)bh*Tt*64;
    int b = bh >> 3, hh = bh & 7;
    uint32_t sK = s2u(Ks), sV = s2u(Vs);

    auto load_kv = [&](int kt, int buf){
        const float* ks = Kb + (size_t)kt*64*64;
        const float* vs = Vb + (size_t)kt*64*64;
        uint32_t kd = sK + buf*64*LDP*4;
        uint32_t vd = sV + buf*64*LDP*4;
#pragma unroll
        for (int i = 0; i < 8; i++) {
            int u = t + i*128;
            int row = u >> 4, seg = u & 15;
            uint32_t off = (uint32_t)((row*LDP + seg*4)*4);
            cp16(kd + off, ks + row*64 + seg*4);
            cp16(vd + off, vs + row*64 + seg*4);
        }
        CP_COMMIT();
    };

    for (int pass = 0; pass < 2; pass++) {
        int qt = pass ? (15 - (int)blockIdx.x) : (int)blockIdx.x;
        int nkt = qt + 1;
        __syncthreads();
        load_kv(0, 0);
        for (int u = t; u < 64*16; u += 128) {
            int row = u >> 4, seg = u & 15;
            *(float4*)&Ps[row*LDP + seg*4] = *(const float4*)(Qb + (size_t)(qt*64+row)*64 + seg*4);
        }
        __syncthreads();
        uint32_t qa[8][4];
        int r0 = w*16 + tq;
#pragma unroll
        for (int ks = 0; ks < 8; ks++) {
            qa[ks][0] = fau(Ps[ r0   *LDP + ks*8+tr  ]);
            qa[ks][1] = fau(Ps[(r0+8)*LDP + ks*8+tr  ]);
            qa[ks][2] = fau(Ps[ r0   *LDP + ks*8+tr+4]);
            qa[ks][3] = fau(Ps[(r0+8)*LDP + ks*8+tr+4]);
        }
        float o[8][4];
#pragma unroll
        for (int j = 0; j < 8; j++)
#pragma unroll
            for (int q = 0; q < 4; q++) o[j][q] = 0.f;
        float m0 = -1e30f, m1 = -1e30f, l0 = 0.f, l1 = 0.f;

        for (int kt = 0; kt < nkt; kt++) {
            int buf = kt & 1;
            __syncthreads();
            if (kt+1 < nkt) { load_kv(kt+1, buf^1); asm volatile("cp.async.wait_group 1;"); }
            else asm volatile("cp.async.wait_group 0;");
            __syncthreads();

            const float* Kt = Ks + buf*64*LDP;
            const float* Vt = Vs + buf*64*LDP;
            float s[8][4];
#pragma unroll
            for (int j = 0; j < 8; j++)
#pragma unroll
                for (int q = 0; q < 4; q++) s[j][q] = 0.f;
#pragma unroll
            for (int nf = 0; nf < 8; nf++) {
#pragma unroll
                for (int ks = 0; ks < 8; ks++) {
                    uint32_t b0 = fau(Kt[(nf*8+tq)*LDP + ks*8+tr  ]);
                    uint32_t b1 = fau(Kt[(nf*8+tq)*LDP + ks*8+tr+4]);
                    MMA8(s[nf], qa[ks], b0, b1);
                }
            }
            if (kt == qt) {
                int qr0 = qt*64 + r0, qr1 = qr0 + 8;
#pragma unroll
                for (int nf = 0; nf < 8; nf++) {
                    int kc = kt*64 + nf*8 + 2*tr;
                    if (kc   > qr0) s[nf][0] = -1e30f;
                    if (kc+1 > qr0) s[nf][1] = -1e30f;
                    if (kc   > qr1) s[nf][2] = -1e30f;
                    if (kc+1 > qr1) s[nf][3] = -1e30f;
                }
            }
            float rm0 = -1e30f, rm1 = -1e30f;
#pragma unroll
            for (int nf = 0; nf < 8; nf++) {
                rm0 = fmaxf(rm0, fmaxf(s[nf][0], s[nf][1]));
                rm1 = fmaxf(rm1, fmaxf(s[nf][2], s[nf][3]));
            }
            rm0 = fmaxf(rm0, __shfl_xor_sync(0xffffffffu, rm0, 1));
            rm0 = fmaxf(rm0, __shfl_xor_sync(0xffffffffu, rm0, 2));
            rm1 = fmaxf(rm1, __shfl_xor_sync(0xffffffffu, rm1, 1));
            rm1 = fmaxf(rm1, __shfl_xor_sync(0xffffffffu, rm1, 2));
            float nm0 = fmaxf(m0, rm0), nm1 = fmaxf(m1, rm1);
            float f0 = __expf(m0 - nm0), f1 = __expf(m1 - nm1);
            float rs0 = 0.f, rs1 = 0.f;
#pragma unroll
            for (int nf = 0; nf < 8; nf++) {
                float p0 = __expf(s[nf][0] - nm0);
                float p1 = __expf(s[nf][1] - nm0);
                float p2 = __expf(s[nf][2] - nm1);
                float p3 = __expf(s[nf][3] - nm1);
                rs0 += p0 + p1; rs1 += p2 + p3;
                Ps[ r0   *LDP + nf*8 + 2*tr    ] = to_tf32(p0);
                Ps[ r0   *LDP + nf*8 + 2*tr + 1] = to_tf32(p1);
                Ps[(r0+8)*LDP + nf*8 + 2*tr    ] = to_tf32(p2);
                Ps[(r0+8)*LDP + nf*8 + 2*tr + 1] = to_tf32(p3);
            }
            rs0 += __shfl_xor_sync(0xffffffffu, rs0, 1);
            rs0 += __shfl_xor_sync(0xffffffffu, rs0, 2);
            rs1 += __shfl_xor_sync(0xffffffffu, rs1, 1);
            rs1 += __shfl_xor_sync(0xffffffffu, rs1, 2);
            l0 = l0*f0 + rs0; m0 = nm0;
            l1 = l1*f1 + rs1; m1 = nm1;
#pragma unroll
            for (int j = 0; j < 8; j++) { o[j][0]*=f0; o[j][1]*=f0; o[j][2]*=f1; o[j][3]*=f1; }
            __syncwarp();
            uint32_t pa[8][4];
#pragma unroll
            for (int ks = 0; ks < 8; ks++) {
                pa[ks][0] = fau(Ps[ r0   *LDP + ks*8+tr  ]);
                pa[ks][1] = fau(Ps[(r0+8)*LDP + ks*8+tr  ]);
                pa[ks][2] = fau(Ps[ r0   *LDP + ks*8+tr+4]);
                pa[ks][3] = fau(Ps[(r0+8)*LDP + ks*8+tr+4]);
            }
#pragma unroll
            for (int nf = 0; nf < 8; nf++) {
#pragma unroll
                for (int ks = 0; ks < 8; ks++) {
                    uint32_t b0 = fau(Vt[(ks*8+tr  )*LDP + nf*8+tq]);
                    uint32_t b1 = fau(Vt[(ks*8+tr+4)*LDP + nf*8+tq]);
                    MMA8(o[nf], pa[ks], b0, b1);
                }
            }
        }
        float il0 = 1.f/l0, il1 = 1.f/l1;
        int qr = qt*64 + r0;
        float* o0 = Out + ((size_t)(b*Tt + qr    ))*Dd + hh*64;
        float* o1 = Out + ((size_t)(b*Tt + qr + 8))*Dd + hh*64;
#pragma unroll
        for (int nf = 0; nf < 8; nf++) {
            int gc = nf*8 + 2*tr;
            float2 a = { to_tf32(o[nf][0]*il0), to_tf32(o[nf][1]*il0) };
            float2 c = { to_tf32(o[nf][2]*il1), to_tf32(o[nf][3]*il1) };
            *(float2*)(o0 + gc) = a;
            *(float2*)(o1 + gc) = c;
        }
    }
}

// ---------------- router (fp32, unrounded input) ------------------------------
__global__ void router_kernel(const float* __restrict__ X, const float* __restrict__ RW,
                              int* __restrict__ cnt, int* __restrict__ tok, float* __restrict__ wt){
    int g = blockIdx.x*blockDim.x + threadIdx.x;
    int warp = g>>5, lane = g&31;
    if (warp >= NT) return;
    const float* xr = X + (size_t)warp*Dd;
    float lg[Ee];
#pragma unroll
    for (int e = 0; e < Ee; e++) {
        const float* w = RW + (size_t)e*Dd;
        float s = 0.f;
        for (int j = lane; j < Dd; j += 32) s += xr[j]*w[j];
        for (int o = 16; o; o >>= 1) s += __shfl_xor_sync(0xffffffffu, s, o);
        lg[e] = s;
    }
    if (lane == 0) {
        int i0 = 0; float v0 = lg[0];
#pragma unroll
        for (int e = 1; e < Ee; e++) if (lg[e] > v0) { v0 = lg[e]; i0 = e; }
        int i1 = -1; float v1 = -3.4e38f;
#pragma unroll
        for (int e = 0; e < Ee; e++) if (e != i0 && lg[e] > v1) { v1 = lg[e]; i1 = e; }
        float e1 = expf(v1 - v0);
        float w0 = 1.f/(1.f+e1), w1 = e1/(1.f+e1);
        int p0 = atomicAdd(&cnt[i0], 1);
        tok[i0*NT+p0] = warp*2;   wt[i0*NT+p0] = w0;
        int p1 = atomicAdd(&cnt[i1], 1);
        tok[i1*NT+p1] = warp*2+1; wt[i1*NT+p1] = w1;
    }
}

// ---------------- host orchestration ------------------------------------------
extern "C" void kernel_launch(void* const* d_in, const int* in_sizes, int n_in,
                              void* d_out, int out_size) {
    (void)in_sizes; (void)n_in; (void)out_size;
    const float* x        = (const float*)d_in[0];
    const float* qkv_w    = (const float*)d_in[1];
    const float* out_w    = (const float*)d_in[2];
    const float* norm1_w  = (const float*)d_in[3];
    const float* norm2_w  = (const float*)d_in[4];
    const float* router_w = (const float*)d_in[5];
    const float* moe_w1   = (const float*)d_in[6];
    const float* moe_w2   = (const float*)d_in[7];
    const float* moe_w3   = (const float*)d_in[8];
    const float* f_w1     = (const float*)d_in[9];
    const float* f_w2     = (const float*)d_in[10];
    const float* f_w3     = (const float*)d_in[11];
    const float* norm_f   = (const float*)d_in[12];
    float* out = (float*)d_out;

    float *h,*xn,*xn32,*qkv,*q,*k,*v,*attn,*hbuf,*wt,*wr;
    int *cnt,*tok;
    cudaGetSymbolAddress((void**)&h, g_h);       cudaGetSymbolAddress((void**)&xn, g_xn);
    cudaGetSymbolAddress((void**)&xn32, g_xn32); cudaGetSymbolAddress((void**)&qkv, g_qkv);
    cudaGetSymbolAddress((void**)&q, g_q);       cudaGetSymbolAddress((void**)&k, g_k);
    cudaGetSymbolAddress((void**)&v, g_v);       cudaGetSymbolAddress((void**)&attn, g_attn);
    cudaGetSymbolAddress((void**)&hbuf, g_hbuf);
    cudaGetSymbolAddress((void**)&wr, g_wr);     cudaGetSymbolAddress((void**)&cnt, g_cnt);
    cudaGetSymbolAddress((void**)&tok, g_tok);   cudaGetSymbolAddress((void**)&wt, g_wt);

    static cudaStream_t s1 = nullptr;
    static cudaEvent_t evF = nullptr, evJ0 = nullptr, evJ1 = nullptr, evJ2 = nullptr;
    if (!s1) {
        cudaStreamCreateWithFlags(&s1, cudaStreamNonBlocking);
        cudaEventCreateWithFlags(&evF,  cudaEventDisableTiming);
        cudaEventCreateWithFlags(&evJ0, cudaEventDisableTiming);
        cudaEventCreateWithFlags(&evJ1, cudaEventDisableTiming);
        cudaEventCreateWithFlags(&evJ2, cudaEventDisableTiming);
    }

    const int attn_smem = 5*64*LDP*sizeof(float);
    cudaFuncSetAttribute(attn_tc_kernel, cudaFuncAttributeMaxDynamicSharedMemorySize, attn_smem);
    const int SM2 = (2*64*36 + 2*128*36)*4;     // 55,296 B
    cudaFuncSetAttribute(mm_kernel<false,false,0>, cudaFuncAttributeMaxDynamicSharedMemorySize, SM2);
    cudaFuncSetAttribute(mm_kernel<false,false,1>, cudaFuncAttributeMaxDynamicSharedMemorySize, SM2);
    cudaFuncSetAttribute(mm_kernel<false,true ,3>, cudaFuncAttributeMaxDynamicSharedMemorySize, SM2);
    cudaFuncSetAttribute(mm_kernel<true ,false,0>, cudaFuncAttributeMaxDynamicSharedMemorySize, SM2);
    cudaFuncSetAttribute(mm_kernel<true ,true ,0>, cudaFuncAttributeMaxDynamicSharedMemorySize, SM2);

    // ---- fork: big weight rounding on s1 -------------------------------------
    cudaEventRecord(evF, 0);
    cudaStreamWaitEvent(s1, evF, 0);
    #define RC(st, src, dstoff, nfl) \
        round_copy<<<(int)(((nfl)/4+255)/256),256,0,st>>>((src), wr+(dstoff), (int)((nfl)/4))
    RC(s1, moe_w1,            OFF_MW1,        SZ_MW1);
    RC(s1, moe_w3,            OFF_MW3,        SZ_MW1);
    RC(s1, moe_w2,            OFF_MW2,        SZ_MW1);
    cudaEventRecord(evJ0, s1);
    RC(s1, f_w1, OFF_FW1, SZ_FW);
    RC(s1, f_w3, OFF_FW3, SZ_FW);
    RC(s1, f_w2, OFF_FW2, SZ_FW);
    cudaEventRecord(evJ1, s1);
    RC(s1, moe_w1+SZ_MW1,     OFF_MW1+SZ_MW1, SZ_MW1);
    RC(s1, moe_w3+SZ_MW1,     OFF_MW3+SZ_MW1, SZ_MW1);
    RC(s1, moe_w2+SZ_MW1,     OFF_MW2+SZ_MW1, SZ_MW1);
    cudaEventRecord(evJ2, s1);

    // ---- main stream ---------------------------------------------------------
    RC((cudaStream_t)0, qkv_w, OFF_QKV, SZ_QKV);
    RC((cudaStream_t)0, out_w, OFF_OUT, SZ_OUT);
    cudaMemcpyAsync(h, x, (size_t)NT*Dd*sizeof(float), cudaMemcpyDeviceToDevice, 0);

    for (int l = 0; l < Ll; l++) {
        rmsnorm_kernel<true><<<NT,256>>>(h, norm1_w+(size_t)l*Dd, xn, nullptr);
        mm_kernel<false,false,0><<<dim3(12,32),128,SM2>>>(
            xn, wr+OFF_QKV+(size_t)l*1536*Dd, nullptr, qkv,
            nullptr,nullptr,nullptr, Dd, 1536, NT, 0,0,0);
        split_rope_kernel<<<(NT*NHh*32+255)/256,256>>>(qkv, q, k, v);
        attn_tc_kernel<<<dim3(8, Bz*NHh),128,attn_smem>>>(q, k, v, attn);
        mm_kernel<false,false,1><<<dim3(4,32),128,SM2>>>(
            attn, wr+OFF_OUT+(size_t)l*Dd*Dd, nullptr, h,
            nullptr,nullptr,nullptr, Dd, Dd, NT, 0,0,0);

        if (l == 0 || l == 2) {
            int m = l/2;
            rmsnorm_kernel<true><<<NT,256>>>(h, norm2_w+(size_t)l*Dd, xn, xn32);
            cudaMemsetAsync(cnt, 0, Ee*sizeof(int), 0);
            router_kernel<<<(NT*32+127)/128,128>>>(xn32, router_w+(size_t)m*Ee*Dd, cnt, tok, wt);
            cudaStreamWaitEvent((cudaStream_t)0, m == 0 ? evJ0 : evJ2, 0);
            mm_kernel<true,true,0><<<dim3(Hh/64,32,Ee),128,SM2>>>(
                xn, wr+OFF_MW1+(size_t)m*SZ_MW1, wr+OFF_MW3+(size_t)m*SZ_MW1, hbuf,
                cnt, tok, nullptr, Dd, Hh, 0, 0, (long long)Hh*Dd, (long long)NT*Hh);
            mm_kernel<false,true,3><<<dim3(4,32,Ee),128,SM2>>>(
                hbuf, wr+OFF_MW2+(size_t)m*SZ_MW1, nullptr, h,
                cnt, tok, wt, Hh, Dd, 0, (long long)NT*Hh, (long long)Dd*Hh, 0);
        } else {
            int m = (l == 1) ? 0 : 1;
            rmsnorm_kernel<true><<<NT,256>>>(h, norm2_w+(size_t)l*Dd, xn, nullptr);
            if (l == 1) cudaStreamWaitEvent((cudaStream_t)0, evJ1, 0);
            mm_kernel<true,false,0><<<dim3(Hh/64,32),128,SM2>>>(
                xn, wr+OFF_FW1+(size_t)m*Hh*Dd, wr+OFF_FW3+(size_t)m*Hh*Dd, hbuf,
                nullptr,nullptr,nullptr, Dd, Hh, NT, 0,0,0);
            mm_kernel<false,false,1><<<dim3(4,32),128,SM2>>>(
                hbuf, wr+OFF_FW2+(size_t)m*Dd*Hh, nullptr, h,
                nullptr,nullptr,nullptr, Hh, Dd, NT, 0,0,0);
        }
    }
    rmsnorm_kernel<false><<<NT,256>>>(h, norm_f, out, nullptr);
}

// round 14
// speedup vs baseline: 1.0818x; 1.0430x over previous
#include <cuda_runtime.h>
#include <math.h>
#include <stdint.h>

#define Bz 2
#define Tt 1024
#define Dd 512
#define NHh 8
#define Ll 4
#define Ee 8
#define Hh 2048
#define NT (Bz*Tt)

#define SZ_QKV ((size_t)Ll*1536*Dd)
#define SZ_OUT ((size_t)Ll*Dd*Dd)
#define SZ_MW  ((size_t)2*Ee*Hh*Dd)
#define SZ_MW1 (SZ_MW/2)
#define SZ_FW  ((size_t)2*Hh*Dd)
#define OFF_QKV 0ull
#define OFF_OUT (OFF_QKV+SZ_QKV)
#define OFF_MW1 (OFF_OUT+SZ_OUT)
#define OFF_MW3 (OFF_MW1+SZ_MW)
#define OFF_MW2 (OFF_MW3+SZ_MW)
#define OFF_FW1 (OFF_MW2+SZ_MW)
#define OFF_FW3 (OFF_FW1+SZ_FW)
#define OFF_FW2 (OFF_FW3+SZ_FW)
#define WR_TOTAL (OFF_FW2+SZ_FW)

__device__ float g_h[NT*Dd];
__device__ float g_xn[NT*Dd];
__device__ float g_xn32[NT*Dd];
__device__ float g_qkv[NT*3*Dd];
__device__ float g_q[NT*Dd];
__device__ float g_k[NT*Dd];
__device__ float g_v[NT*Dd];
__device__ float g_attn[NT*Dd];
__device__ float g_hbuf[(size_t)Ee*NT*Hh];
__device__ float g_wr[WR_TOTAL];
__device__ int   g_cnt[Ee];
__device__ int   g_tok[Ee*NT];
__device__ float g_wt[Ee*NT];

// ---------------- helpers -----------------------------------------------------
__device__ __forceinline__ uint32_t s2u(const void* p){
    uint32_t a;
    asm("{ .reg .u64 t; cvta.to.shared.u64 t, %1; cvt.u32.u64 %0, t; }":"=r"(a):"l"(p));
    return a;
}
__device__ __forceinline__ float to_tf32(float x){
    uint32_t u; asm("cvt.rn.tf32.f32 %0, %1;":"=r"(u):"f"(x));
    return __uint_as_float(u);
}
__device__ __forceinline__ void cp16(uint32_t dst, const void* src){
    asm volatile("cp.async.cg.shared.global [%0], [%1], 16;"::"r"(dst),"l"(src));
}
#define CP_COMMIT() asm volatile("cp.async.commit_group;")
#define fau __float_as_uint

#define MMA8(d,a,b0,b1) \
  asm volatile("mma.sync.aligned.m16n8k8.row.col.f32.tf32.tf32.f32 " \
    "{%0,%1,%2,%3},{%4,%5,%6,%7},{%8,%9},{%0,%1,%2,%3};" \
    : "+f"((d)[0]),"+f"((d)[1]),"+f"((d)[2]),"+f"((d)[3]) \
    : "r"((a)[0]),"r"((a)[1]),"r"((a)[2]),"r"((a)[3]),"r"(b0),"r"(b1))

// ============ tf32 mma.sync GEMM v4b: C = A @ B^T =============================
// CTA: 128 threads (4 warps, 2x2). CTA tile 64 rows x (FUSED?64:128) cols.
// Warp tile 32 x 64 (non-fused) / 32 x 32 dual (fused).
// K-chunk 32, stride 36, 3-stage cp.async pipeline, ONE barrier per chunk.
// Drain fix: last iteration must use wait_group 0 (its own load is the only
// pending group and wait_group 1 would not wait for it).
// MODE 0 store, 1 +=, 3 weighted atomic scatter-add into token rows.
template<bool FUSED, bool GROUPED, int MODE>
__global__ void __launch_bounds__(128) mm_kernel(
    const float* __restrict__ A, const float* __restrict__ B1, const float* __restrict__ B3,
    float* __restrict__ C, const int* __restrict__ cnt, const int* __restrict__ tok,
    const float* __restrict__ wtv, int K, int ldc, int nrows,
    long long sAe, long long sBe, long long sCe)
{
    constexpr int NCOLS = FUSED ? 64 : 128;
    constexpr int NJ    = NCOLS/16;            // n-frags per warp (8 or 4)
    constexpr int LDS   = 36;
    extern __shared__ float sm[];
    float* As = sm;                            // [3][64][36]
    float* Bs = sm + 3*64*LDS;                 // [3][128][36]

    int e = GROUPED ? blockIdx.z : 0;
    int n = GROUPED ? cnt[e] : nrows;
    int rb = blockIdx.y*64;
    if (rb >= n) return;
    int cb = blockIdx.x*NCOLS;
    if (GROUPED) {
        if (!FUSED) A += (size_t)e*sAe;
        B1 += (size_t)e*sBe;
        if (FUSED) B3 += (size_t)e*sBe;
        C += (size_t)e*sCe;
    }
    int t = threadIdx.x;
    int lane = t & 31, w = t >> 5;
    int wr = w >> 1, wc = w & 1;               // 2x2 warp grid
    int tq = lane >> 2, tr = lane & 3;

    const float* Ap[4]; const float* Bp[8];
#pragma unroll
    for (int i = 0; i < 4; i++) {
        int lin = t + i*128;
        int row = lin >> 3, kq = (lin & 7) << 2;
        int ar = rb + row; if (GROUPED && ar > n-1) ar = n-1;
        if (GROUPED && FUSED) Ap[i] = A + (size_t)(tok[(size_t)e*NT + ar] >> 1)*K + kq;
        else                  Ap[i] = A + (size_t)ar*K + kq;
    }
#pragma unroll
    for (int i = 0; i < 8; i++) {
        int lin = t + i*128;
        int row = lin >> 3, kq = (lin & 7) << 2;
        if (!FUSED) Bp[i] = B1 + (size_t)(cb + row)*K + kq;
        else {
            const float* bb = (row < 64) ? B1 : B3;
            Bp[i] = bb + (size_t)(cb + (row & 63))*K + kq;
        }
    }
    uint32_t sA = s2u(As), sB = s2u(Bs);

    float acc1[2][NJ][4];
    float acc3[FUSED?2:1][NJ][4];
#pragma unroll
    for (int i = 0; i < 2; i++)
#pragma unroll
        for (int j = 0; j < NJ; j++)
#pragma unroll
            for (int q = 0; q < 4; q++) { acc1[i][j][q] = 0.f; if (FUSED) acc3[i][j][q] = 0.f; }

    auto load = [&](int c, int s){
#pragma unroll
        for (int i = 0; i < 4; i++) {
            int lin = t + i*128;
            int row = lin >> 3, kq = (lin & 7) << 2;
            cp16(sA + (uint32_t)(((s*64 + row)*LDS + kq)*4), Ap[i] + (size_t)c*32);
        }
#pragma unroll
        for (int i = 0; i < 8; i++) {
            int lin = t + i*128;
            int row = lin >> 3, kq = (lin & 7) << 2;
            cp16(sB + (uint32_t)(((s*128 + row)*LDS + kq)*4), Bp[i] + (size_t)c*32);
        }
        CP_COMMIT();
    };

    const int NC = K >> 5;                      // >= 16 always here
    load(0, 0);
    load(1, 1);
    for (int c = 0; c < NC; c++) {
        // groups newer than c still allowed pending: 1 in steady state, 0 at tail
        if (c+1 < NC) asm volatile("cp.async.wait_group 1;");
        else          asm volatile("cp.async.wait_group 0;");
        __syncthreads();                        // chunk-c visible; compute(c-1) done before load(c+2) overwrite
        if (c+2 < NC) load(c+2, (c+2)%3);
        int s = c % 3;
        const float* Ab = As + (size_t)s*64*LDS;
        const float* Bb = Bs + (size_t)s*128*LDS;
#pragma unroll
        for (int ks = 0; ks < 4; ks++) {
            int k0 = ks*8;
            uint32_t a[2][4];
#pragma unroll
            for (int i = 0; i < 2; i++) {
                int r0 = wr*32 + i*16;
                a[i][0] = fau(Ab[(r0+tq  )*LDS + k0+tr  ]);
                a[i][1] = fau(Ab[(r0+tq+8)*LDS + k0+tr  ]);
                a[i][2] = fau(Ab[(r0+tq  )*LDS + k0+tr+4]);
                a[i][3] = fau(Ab[(r0+tq+8)*LDS + k0+tr+4]);
            }
#pragma unroll
            for (int j = 0; j < NJ; j++) {
                int bc = wc*(NJ*8) + j*8 + tq;
                uint32_t b0 = fau(Bb[bc*LDS + k0+tr]);
                uint32_t b1 = fau(Bb[bc*LDS + k0+tr+4]);
#pragma unroll
                for (int i = 0; i < 2; i++) MMA8(acc1[i][j], a[i], b0, b1);
                if (FUSED) {
                    uint32_t c0 = fau(Bb[(bc+64)*LDS + k0+tr]);
                    uint32_t c1 = fau(Bb[(bc+64)*LDS + k0+tr+4]);
#pragma unroll
                    for (int i = 0; i < 2; i++) MMA8(acc3[i][j], a[i], c0, c1);
                }
            }
        }
    }

    // -------- epilogue --------
#pragma unroll
    for (int i = 0; i < 2; i++)
#pragma unroll
        for (int hh = 0; hh < 2; hh++) {
            int gr = rb + wr*32 + i*16 + tq + hh*8;
            if (GROUPED && gr >= n) continue;
            int orow = gr; float wv = 1.f;
            if (GROUPED && MODE == 3) {
                int pk = tok[(size_t)e*NT + gr];
                wv   = wtv[(size_t)e*NT + gr];
                orow = pk >> 1;
            }
            float* cr = C + (size_t)orow*ldc;
#pragma unroll
            for (int j = 0; j < NJ; j++) {
                int gc = cb + wc*(NJ*8) + j*8 + tr*2;
                float v0 = acc1[i][j][hh*2], v1 = acc1[i][j][hh*2+1];
                if (FUSED) {
                    float u0 = acc3[i][j][hh*2], u1 = acc3[i][j][hh*2+1];
                    float2 o;
                    o.x = to_tf32(v0/(1.f+__expf(-v0))*u0);
                    o.y = to_tf32(v1/(1.f+__expf(-v1))*u1);
                    *(float2*)(cr + gc) = o;
                } else if (MODE == 0) {
                    float2 o = {v0, v1};
                    *(float2*)(cr + gc) = o;
                } else if (MODE == 1) {
                    float2 o = *(float2*)(cr + gc);
                    o.x += v0; o.y += v1;
                    *(float2*)(cr + gc) = o;
                } else {
                    atomicAdd(cr + gc,     wv*v0);
                    atomicAdd(cr + gc + 1, wv*v1);
                }
            }
        }
}

// ---------------- weight rounding fp32 -> RN tf32 ----------------------------
__global__ void round_copy(const float* __restrict__ s, float* __restrict__ d, int n4){
    int i = blockIdx.x*256 + threadIdx.x;
    if (i >= n4) return;
    float4 v = ((const float4*)s)[i];
    v.x=to_tf32(v.x); v.y=to_tf32(v.y); v.z=to_tf32(v.z); v.w=to_tf32(v.w);
    ((float4*)d)[i] = v;
}

// ---------------- rmsnorm ------------------------------------------------------
template<bool ROUND>
__global__ void rmsnorm_kernel(const float* __restrict__ in, const float* __restrict__ w,
                               float* __restrict__ out, float* __restrict__ out32){
    int row = blockIdx.x;
    const float* x = in + (size_t)row*Dd;
    float s = 0.f;
    for (int j = threadIdx.x; j < Dd; j += 256) { float v = x[j]; s += v*v; }
    __shared__ float red[8];
    for (int o = 16; o; o >>= 1) s += __shfl_xor_sync(0xffffffffu, s, o);
    if ((threadIdx.x & 31) == 0) red[threadIdx.x>>5] = s;
    __syncthreads();
    if (threadIdx.x < 8) {
        float v = red[threadIdx.x];
        for (int o = 4; o; o >>= 1) v += __shfl_xor_sync(0xffu, v, o);
        if (threadIdx.x == 0) red[0] = v;
    }
    __syncthreads();
    float rms = rsqrtf(red[0]/(float)Dd + 1e-5f);
    for (int j = threadIdx.x; j < Dd; j += 256) {
        float v = w[j]*x[j]*rms;
        out[(size_t)row*Dd+j] = ROUND ? to_tf32(v) : v;
        if (out32) out32[(size_t)row*Dd+j] = v;
    }
}

// ---------------- qkv split + RoPE (RN-tf32 outputs, Q pre-scaled) ------------
__global__ void split_rope_kernel(const float* __restrict__ qkv, float* __restrict__ Q,
                                  float* __restrict__ K, float* __restrict__ V){
    int idx = blockIdx.x*256 + threadIdx.x;
    if (idx >= NT*NHh*32) return;
    int d = idx & 31, h = (idx>>5)&7, bt = idx>>8;
    int tt = bt & (Tt-1), b = bt>>10;
    float inv = expf(-(float)d*0.28782313662425575f);
    float sn, cs; sincosf((float)tt*inv, &sn, &cs);
    size_t bi = (size_t)bt*1536 + h*64 + d;
    float q1=qkv[bi], q2=qkv[bi+32], k1=qkv[bi+512], k2=qkv[bi+544], v1=qkv[bi+1024], v2=qkv[bi+1056];
    size_t oi = ((size_t)(b*NHh+h)*Tt + tt)*64 + d;
    Q[oi]   =to_tf32((q1*cs-q2*sn)*0.125f); Q[oi+32]=to_tf32((q1*sn+q2*cs)*0.125f);
    K[oi]   =to_tf32(k1*cs-k2*sn);          K[oi+32]=to_tf32(k1*sn+k2*cs);
    V[oi]   =to_tf32(v1);                   V[oi+32]=to_tf32(v2);
}

// ---------------- tensor-core flash attention (causal, HD=64) -----------------
#define LDP 72
__global__ void __launch_bounds__(128) attn_tc_kernel(
    const float* __restrict__ Q, const float* __restrict__ K,
    const float* __restrict__ V, float* __restrict__ Out)
{
    extern __shared__ float sm[];
    float* Ks = sm;
    float* Vs = sm + 2*64*LDP;
    float* Ps = sm + 4*64*LDP;
    int bh = blockIdx.y;
    int t = threadIdx.x, lane = t & 31, w = t >> 5;
    int tq = lane >> 2, tr = lane & 3;
    const float* Qb = Q + (size_t)bh*Tt*64;
    const float* Kb = K + (size_t)bh*Tt*64;
    const float* Vb = V + (size_t)bh*Tt*64;
    int b = bh >> 3, hh = bh & 7;
    uint32_t sK = s2u(Ks), sV = s2u(Vs);

    auto load_kv = [&](int kt, int buf){
        const float* ks = Kb + (size_t)kt*64*64;
        const float* vs = Vb + (size_t)kt*64*64;
        uint32_t kd = sK + buf*64*LDP*4;
        uint32_t vd = sV + buf*64*LDP*4;
#pragma unroll
        for (int i = 0; i < 8; i++) {
            int u = t + i*128;
            int row = u >> 4, seg = u & 15;
            uint32_t off = (uint32_t)((row*LDP + seg*4)*4);
            cp16(kd + off, ks + row*64 + seg*4);
            cp16(vd + off, vs + row*64 + seg*4);
        }
        CP_COMMIT();
    };

    for (int pass = 0; pass < 2; pass++) {
        int qt = pass ? (15 - (int)blockIdx.x) : (int)blockIdx.x;
        int nkt = qt + 1;
        __syncthreads();
        load_kv(0, 0);
        for (int u = t; u < 64*16; u += 128) {
            int row = u >> 4, seg = u & 15;
            *(float4*)&Ps[row*LDP + seg*4] = *(const float4*)(Qb + (size_t)(qt*64+row)*64 + seg*4);
        }
        __syncthreads();
        uint32_t qa[8][4];
        int r0 = w*16 + tq;
#pragma unroll
        for (int ks = 0; ks < 8; ks++) {
            qa[ks][0] = fau(Ps[ r0   *LDP + ks*8+tr  ]);
            qa[ks][1] = fau(Ps[(r0+8)*LDP + ks*8+tr  ]);
            qa[ks][2] = fau(Ps[ r0   *LDP + ks*8+tr+4]);
            qa[ks][3] = fau(Ps[(r0+8)*LDP + ks*8+tr+4]);
        }
        float o[8][4];
#pragma unroll
        for (int j = 0; j < 8; j++)
#pragma unroll
            for (int q = 0; q < 4; q++) o[j][q] = 0.f;
        float m0 = -1e30f, m1 = -1e30f, l0 = 0.f, l1 = 0.f;

        for (int kt = 0; kt < nkt; kt++) {
            int buf = kt & 1;
            __syncthreads();
            if (kt+1 < nkt) { load_kv(kt+1, buf^1); asm volatile("cp.async.wait_group 1;"); }
            else asm volatile("cp.async.wait_group 0;");
            __syncthreads();

            const float* Kt = Ks + buf*64*LDP;
            const float* Vt = Vs + buf*64*LDP;
            float s[8][4];
#pragma unroll
            for (int j = 0; j < 8; j++)
#pragma unroll
                for (int q = 0; q < 4; q++) s[j][q] = 0.f;
#pragma unroll
            for (int nf = 0; nf < 8; nf++) {
#pragma unroll
                for (int ks = 0; ks < 8; ks++) {
                    uint32_t b0 = fau(Kt[(nf*8+tq)*LDP + ks*8+tr  ]);
                    uint32_t b1 = fau(Kt[(nf*8+tq)*LDP + ks*8+tr+4]);
                    MMA8(s[nf], qa[ks], b0, b1);
                }
            }
            if (kt == qt) {
                int qr0 = qt*64 + r0, qr1 = qr0 + 8;
#pragma unroll
                for (int nf = 0; nf < 8; nf++) {
                    int kc = kt*64 + nf*8 + 2*tr;
                    if (kc   > qr0) s[nf][0] = -1e30f;
                    if (kc+1 > qr0) s[nf][1] = -1e30f;
                    if (kc   > qr1) s[nf][2] = -1e30f;
                    if (kc+1 > qr1) s[nf][3] = -1e30f;
                }
            }
            float rm0 = -1e30f, rm1 = -1e30f;
#pragma unroll
            for (int nf = 0; nf < 8; nf++) {
                rm0 = fmaxf(rm0, fmaxf(s[nf][0], s[nf][1]));
                rm1 = fmaxf(rm1, fmaxf(s[nf][2], s[nf][3]));
            }
            rm0 = fmaxf(rm0, __shfl_xor_sync(0xffffffffu, rm0, 1));
            rm0 = fmaxf(rm0, __shfl_xor_sync(0xffffffffu, rm0, 2));
            rm1 = fmaxf(rm1, __shfl_xor_sync(0xffffffffu, rm1, 1));
            rm1 = fmaxf(rm1, __shfl_xor_sync(0xffffffffu, rm1, 2));
            float nm0 = fmaxf(m0, rm0), nm1 = fmaxf(m1, rm1);
            float f0 = __expf(m0 - nm0), f1 = __expf(m1 - nm1);
            float rs0 = 0.f, rs1 = 0.f;
#pragma unroll
            for (int nf = 0; nf < 8; nf++) {
                float p0 = __expf(s[nf][0] - nm0);
                float p1 = __expf(s[nf][1] - nm0);
                float p2 = __expf(s[nf][2] - nm1);
                float p3 = __expf(s[nf][3] - nm1);
                rs0 += p0 + p1; rs1 += p2 + p3;
                Ps[ r0   *LDP + nf*8 + 2*tr    ] = to_tf32(p0);
                Ps[ r0   *LDP + nf*8 + 2*tr + 1] = to_tf32(p1);
                Ps[(r0+8)*LDP + nf*8 + 2*tr    ] = to_tf32(p2);
                Ps[(r0+8)*LDP + nf*8 + 2*tr + 1] = to_tf32(p3);
            }
            rs0 += __shfl_xor_sync(0xffffffffu, rs0, 1);
            rs0 += __shfl_xor_sync(0xffffffffu, rs0, 2);
            rs1 += __shfl_xor_sync(0xffffffffu, rs1, 1);
            rs1 += __shfl_xor_sync(0xffffffffu, rs1, 2);
            l0 = l0*f0 + rs0; m0 = nm0;
            l1 = l1*f1 + rs1; m1 = nm1;
#pragma unroll
            for (int j = 0; j < 8; j++) { o[j][0]*=f0; o[j][1]*=f0; o[j][2]*=f1; o[j][3]*=f1; }
            __syncwarp();
            uint32_t pa[8][4];
#pragma unroll
            for (int ks = 0; ks < 8; ks++) {
                pa[ks][0] = fau(Ps[ r0   *LDP + ks*8+tr  ]);
                pa[ks][1] = fau(Ps[(r0+8)*LDP + ks*8+tr  ]);
                pa[ks][2] = fau(Ps[ r0   *LDP + ks*8+tr+4]);
                pa[ks][3] = fau(Ps[(r0+8)*LDP + ks*8+tr+4]);
            }
#pragma unroll
            for (int nf = 0; nf < 8; nf++) {
#pragma unroll
                for (int ks = 0; ks < 8; ks++) {
                    uint32_t b0 = fau(Vt[(ks*8+tr  )*LDP + nf*8+tq]);
                    uint32_t b1 = fau(Vt[(ks*8+tr+4)*LDP + nf*8+tq]);
                    MMA8(o[nf], pa[ks], b0, b1);
                }
            }
        }
        float il0 = 1.f/l0, il1 = 1.f/l1;
        int qr = qt*64 + r0;
        float* o0 = Out + ((size_t)(b*Tt + qr    ))*Dd + hh*64;
        float* o1 = Out + ((size_t)(b*Tt + qr + 8))*Dd + hh*64;
#pragma unroll
        for (int nf = 0; nf < 8; nf++) {
            int gc = nf*8 + 2*tr;
            float2 a = { to_tf32(o[nf][0]*il0), to_tf32(o[nf][1]*il0) };
            float2 c = { to_tf32(o[nf][2]*il1), to_tf32(o[nf][3]*il1) };
            *(float2*)(o0 + gc) = a;
            *(float2*)(o1 + gc) = c;
        }
    }
}

// ---------------- router (fp32, unrounded input) ------------------------------
__global__ void router_kernel(const float* __restrict__ X, const float* __restrict__ RW,
                              int* __restrict__ cnt, int* __restrict__ tok, float* __restrict__ wt){
    int g = blockIdx.x*blockDim.x + threadIdx.x;
    int warp = g>>5, lane = g&31;
    if (warp >= NT) return;
    const float* xr = X + (size_t)warp*Dd;
    float lg[Ee];
#pragma unroll
    for (int e = 0; e < Ee; e++) {
        const float* w = RW + (size_t)e*Dd;
        float s = 0.f;
        for (int j = lane; j < Dd; j += 32) s += xr[j]*w[j];
        for (int o = 16; o; o >>= 1) s += __shfl_xor_sync(0xffffffffu, s, o);
        lg[e] = s;
    }
    if (lane == 0) {
        int i0 = 0; float v0 = lg[0];
#pragma unroll
        for (int e = 1; e < Ee; e++) if (lg[e] > v0) { v0 = lg[e]; i0 = e; }
        int i1 = -1; float v1 = -3.4e38f;
#pragma unroll
        for (int e = 0; e < Ee; e++) if (e != i0 && lg[e] > v1) { v1 = lg[e]; i1 = e; }
        float e1 = expf(v1 - v0);
        float w0 = 1.f/(1.f+e1), w1 = e1/(1.f+e1);
        int p0 = atomicAdd(&cnt[i0], 1);
        tok[i0*NT+p0] = warp*2;   wt[i0*NT+p0] = w0;
        int p1 = atomicAdd(&cnt[i1], 1);
        tok[i1*NT+p1] = warp*2+1; wt[i1*NT+p1] = w1;
    }
}

// ---------------- host orchestration ------------------------------------------
extern "C" void kernel_launch(void* const* d_in, const int* in_sizes, int n_in,
                              void* d_out, int out_size) {
    (void)in_sizes; (void)n_in; (void)out_size;
    const float* x        = (const float*)d_in[0];
    const float* qkv_w    = (const float*)d_in[1];
    const float* out_w    = (const float*)d_in[2];
    const float* norm1_w  = (const float*)d_in[3];
    const float* norm2_w  = (const float*)d_in[4];
    const float* router_w = (const float*)d_in[5];
    const float* moe_w1   = (const float*)d_in[6];
    const float* moe_w2   = (const float*)d_in[7];
    const float* moe_w3   = (const float*)d_in[8];
    const float* f_w1     = (const float*)d_in[9];
    const float* f_w2     = (const float*)d_in[10];
    const float* f_w3     = (const float*)d_in[11];
    const float* norm_f   = (const float*)d_in[12];
    float* out = (float*)d_out;

    float *h,*xn,*xn32,*qkv,*q,*k,*v,*attn,*hbuf,*wt,*wr;
    int *cnt,*tok;
    cudaGetSymbolAddress((void**)&h, g_h);       cudaGetSymbolAddress((void**)&xn, g_xn);
    cudaGetSymbolAddress((void**)&xn32, g_xn32); cudaGetSymbolAddress((void**)&qkv, g_qkv);
    cudaGetSymbolAddress((void**)&q, g_q);       cudaGetSymbolAddress((void**)&k, g_k);
    cudaGetSymbolAddress((void**)&v, g_v);       cudaGetSymbolAddress((void**)&attn, g_attn);
    cudaGetSymbolAddress((void**)&hbuf, g_hbuf);
    cudaGetSymbolAddress((void**)&wr, g_wr);     cudaGetSymbolAddress((void**)&cnt, g_cnt);
    cudaGetSymbolAddress((void**)&tok, g_tok);   cudaGetSymbolAddress((void**)&wt, g_wt);

    static cudaStream_t s1 = nullptr;
    static cudaEvent_t evF = nullptr, evJ0 = nullptr, evJ1 = nullptr, evJ2 = nullptr;
    if (!s1) {
        cudaStreamCreateWithFlags(&s1, cudaStreamNonBlocking);
        cudaEventCreateWithFlags(&evF,  cudaEventDisableTiming);
        cudaEventCreateWithFlags(&evJ0, cudaEventDisableTiming);
        cudaEventCreateWithFlags(&evJ1, cudaEventDisableTiming);
        cudaEventCreateWithFlags(&evJ2, cudaEventDisableTiming);
    }

    const int attn_smem = 5*64*LDP*sizeof(float);
    cudaFuncSetAttribute(attn_tc_kernel, cudaFuncAttributeMaxDynamicSharedMemorySize, attn_smem);
    const int SM3 = (3*64*36 + 3*128*36)*4;     // 82,944 B
    cudaFuncSetAttribute(mm_kernel<false,false,0>, cudaFuncAttributeMaxDynamicSharedMemorySize, SM3);
    cudaFuncSetAttribute(mm_kernel<false,false,1>, cudaFuncAttributeMaxDynamicSharedMemorySize, SM3);
    cudaFuncSetAttribute(mm_kernel<false,true ,3>, cudaFuncAttributeMaxDynamicSharedMemorySize, SM3);
    cudaFuncSetAttribute(mm_kernel<true ,false,0>, cudaFuncAttributeMaxDynamicSharedMemorySize, SM3);
    cudaFuncSetAttribute(mm_kernel<true ,true ,0>, cudaFuncAttributeMaxDynamicSharedMemorySize, SM3);

    // ---- fork: big weight rounding on s1 -------------------------------------
    cudaEventRecord(evF, 0);
    cudaStreamWaitEvent(s1, evF, 0);
    #define RC(st, src, dstoff, nfl) \
        round_copy<<<(int)(((nfl)/4+255)/256),256,0,st>>>((src), wr+(dstoff), (int)((nfl)/4))
    RC(s1, moe_w1,            OFF_MW1,        SZ_MW1);
    RC(s1, moe_w3,            OFF_MW3,        SZ_MW1);
    RC(s1, moe_w2,            OFF_MW2,        SZ_MW1);
    cudaEventRecord(evJ0, s1);
    RC(s1, f_w1, OFF_FW1, SZ_FW);
    RC(s1, f_w3, OFF_FW3, SZ_FW);
    RC(s1, f_w2, OFF_FW2, SZ_FW);
    cudaEventRecord(evJ1, s1);
    RC(s1, moe_w1+SZ_MW1,     OFF_MW1+SZ_MW1, SZ_MW1);
    RC(s1, moe_w3+SZ_MW1,     OFF_MW3+SZ_MW1, SZ_MW1);
    RC(s1, moe_w2+SZ_MW1,     OFF_MW2+SZ_MW1, SZ_MW1);
    cudaEventRecord(evJ2, s1);

    // ---- main stream ---------------------------------------------------------
    RC((cudaStream_t)0, qkv_w, OFF_QKV, SZ_QKV);
    RC((cudaStream_t)0, out_w, OFF_OUT, SZ_OUT);
    cudaMemcpyAsync(h, x, (size_t)NT*Dd*sizeof(float), cudaMemcpyDeviceToDevice, 0);

    for (int l = 0; l < Ll; l++) {
        rmsnorm_kernel<true><<<NT,256>>>(h, norm1_w+(size_t)l*Dd, xn, nullptr);
        mm_kernel<false,false,0><<<dim3(12,32),128,SM3>>>(
            xn, wr+OFF_QKV+(size_t)l*1536*Dd, nullptr, qkv,
            nullptr,nullptr,nullptr, Dd, 1536, NT, 0,0,0);
        split_rope_kernel<<<(NT*NHh*32+255)/256,256>>>(qkv, q, k, v);
        attn_tc_kernel<<<dim3(8, Bz*NHh),128,attn_smem>>>(q, k, v, attn);
        mm_kernel<false,false,1><<<dim3(4,32),128,SM3>>>(
            attn, wr+OFF_OUT+(size_t)l*Dd*Dd, nullptr, h,
            nullptr,nullptr,nullptr, Dd, Dd, NT, 0,0,0);

        if (l == 0 || l == 2) {
            int m = l/2;
            rmsnorm_kernel<true><<<NT,256>>>(h, norm2_w+(size_t)l*Dd, xn, xn32);
            cudaMemsetAsync(cnt, 0, Ee*sizeof(int), 0);
            router_kernel<<<(NT*32+127)/128,128>>>(xn32, router_w+(size_t)m*Ee*Dd, cnt, tok, wt);
            cudaStreamWaitEvent((cudaStream_t)0, m == 0 ? evJ0 : evJ2, 0);
            mm_kernel<true,true,0><<<dim3(Hh/64,32,Ee),128,SM3>>>(
                xn, wr+OFF_MW1+(size_t)m*SZ_MW1, wr+OFF_MW3+(size_t)m*SZ_MW1, hbuf,
                cnt, tok, nullptr, Dd, Hh, 0, 0, (long long)Hh*Dd, (long long)NT*Hh);
            mm_kernel<false,true,3><<<dim3(4,32,Ee),128,SM3>>>(
                hbuf, wr+OFF_MW2+(size_t)m*SZ_MW1, nullptr, h,
                cnt, tok, wt, Hh, Dd, 0, (long long)NT*Hh, (long long)Dd*Hh, 0);
        } else {
            int m = (l == 1) ? 0 : 1;
            rmsnorm_kernel<true><<<NT,256>>>(h, norm2_w+(size_t)l*Dd, xn, nullptr);
            if (l == 1) cudaStreamWaitEvent((cudaStream_t)0, evJ1, 0);
            mm_kernel<true,false,0><<<dim3(Hh/64,32),128,SM3>>>(
                xn, wr+OFF_FW1+(size_t)m*Hh*Dd, wr+OFF_FW3+(size_t)m*Hh*Dd, hbuf,
                nullptr,nullptr,nullptr, Dd, Hh, NT, 0,0,0);
            mm_kernel<false,false,1><<<dim3(4,32),128,SM3>>>(
                hbuf, wr+OFF_FW2+(size_t)m*Dd*Hh, nullptr, h,
                nullptr,nullptr,nullptr, Hh, Dd, NT, 0,0,0);
        }
    }
    rmsnorm_kernel<false><<<NT,256>>>(h, norm_f, out, nullptr);
}

// round 15
// speedup vs baseline: 1.0888x; 1.0064x over previous
#include <cuda_runtime.h>
#include <math.h>
#include <stdint.h>

#define Bz 2
#define Tt 1024
#define Dd 512
#define NHh 8
#define Ll 4
#define Ee 8
#define Hh 2048
#define NT (Bz*Tt)

#define SZ_QKV ((size_t)Ll*1536*Dd)
#define SZ_OUT ((size_t)Ll*Dd*Dd)
#define SZ_MW  ((size_t)2*Ee*Hh*Dd)
#define SZ_MW1 (SZ_MW/2)
#define SZ_FW  ((size_t)2*Hh*Dd)
#define OFF_QKV 0ull
#define OFF_OUT (OFF_QKV+SZ_QKV)
#define OFF_MW1 (OFF_OUT+SZ_OUT)
#define OFF_MW3 (OFF_MW1+SZ_MW)
#define OFF_MW2 (OFF_MW3+SZ_MW)
#define OFF_FW1 (OFF_MW2+SZ_MW)
#define OFF_FW3 (OFF_FW1+SZ_FW)
#define OFF_FW2 (OFF_FW3+SZ_FW)
#define WR_TOTAL (OFF_FW2+SZ_FW)

__device__ float g_h[NT*Dd];
__device__ float g_xn[NT*Dd];
__device__ float g_xn32[NT*Dd];
__device__ float g_q[NT*Dd];
__device__ float g_k[NT*Dd];
__device__ float g_v[NT*Dd];
__device__ float g_attn[NT*Dd];
__device__ float g_hbuf[(size_t)Ee*NT*Hh];
__device__ float g_wr[WR_TOTAL];
__device__ float g_cos[Tt*32];
__device__ float g_sin[Tt*32];
__device__ int   g_cnt[Ee];
__device__ int   g_tok[Ee*NT];
__device__ float g_wt[Ee*NT];

// ---------------- helpers -----------------------------------------------------
__device__ __forceinline__ uint32_t s2u(const void* p){
    uint32_t a;
    asm("{ .reg .u64 t; cvta.to.shared.u64 t, %1; cvt.u32.u64 %0, t; }":"=r"(a):"l"(p));
    return a;
}
__device__ __forceinline__ float to_tf32(float x){
    uint32_t u; asm("cvt.rn.tf32.f32 %0, %1;":"=r"(u):"f"(x));
    return __uint_as_float(u);
}
__device__ __forceinline__ void cp16(uint32_t dst, const void* src){
    asm volatile("cp.async.cg.shared.global [%0], [%1], 16;"::"r"(dst),"l"(src));
}
#define CP_COMMIT() asm volatile("cp.async.commit_group;")
#define fau __float_as_uint

#define MMA8(d,a,b0,b1) \
  asm volatile("mma.sync.aligned.m16n8k8.row.col.f32.tf32.tf32.f32 " \
    "{%0,%1,%2,%3},{%4,%5,%6,%7},{%8,%9},{%0,%1,%2,%3};" \
    : "+f"((d)[0]),"+f"((d)[1]),"+f"((d)[2]),"+f"((d)[3]) \
    : "r"((a)[0]),"r"((a)[1]),"r"((a)[2]),"r"((a)[3]),"r"(b0),"r"(b1))

// ============ tf32 mma.sync GEMM v5: C = A @ B^T ==============================
// CTA: 128 threads (4 warps, 2x2). CTA tile 64 rows x (FUSED?64:128) cols.
// Warp tile 32 x 64 (non-fused) / 32 x 32 dual (fused).
// K-chunk 32, stride 36, 3-stage cp.async pipeline, ONE barrier per chunk
// (drain: last iteration waits group 0).
// MODE 0 store, 1 +=, 3 weighted atomic scatter-add, 4 fused RoPE qkv-split.
template<bool FUSED, bool GROUPED, int MODE>
__global__ void __launch_bounds__(128) mm_kernel(
    const float* __restrict__ A, const float* __restrict__ B1, const float* __restrict__ B3,
    float* __restrict__ C, const int* __restrict__ cnt, const int* __restrict__ tok,
    const float* __restrict__ wtv, int K, int ldc, int nrows,
    long long sAe, long long sBe, long long sCe)
{
    constexpr int NCOLS = FUSED ? 64 : 128;
    constexpr int NJ    = NCOLS/16;            // n-frags per warp (8 or 4)
    constexpr int LDS   = 36;
    extern __shared__ float sm[];
    float* As = sm;                            // [3][64][36]
    float* Bs = sm + 3*64*LDS;                 // [3][128][36]

    int e = GROUPED ? blockIdx.z : 0;
    int n = GROUPED ? cnt[e] : nrows;
    int rb = blockIdx.y*64;
    if (rb >= n) return;
    int cb = blockIdx.x*NCOLS;
    if (GROUPED) {
        if (!FUSED) A += (size_t)e*sAe;
        B1 += (size_t)e*sBe;
        if (FUSED) B3 += (size_t)e*sBe;
        C += (size_t)e*sCe;
    }
    int t = threadIdx.x;
    int lane = t & 31, w = t >> 5;
    int wr = w >> 1, wc = w & 1;               // 2x2 warp grid
    int tq = lane >> 2, tr = lane & 3;

    const float* Ap[4]; const float* Bp[8];
#pragma unroll
    for (int i = 0; i < 4; i++) {
        int lin = t + i*128;
        int row = lin >> 3, kq = (lin & 7) << 2;
        int ar = rb + row; if (GROUPED && ar > n-1) ar = n-1;
        if (GROUPED && FUSED) Ap[i] = A + (size_t)(tok[(size_t)e*NT + ar] >> 1)*K + kq;
        else                  Ap[i] = A + (size_t)ar*K + kq;
    }
#pragma unroll
    for (int i = 0; i < 8; i++) {
        int lin = t + i*128;
        int row = lin >> 3, kq = (lin & 7) << 2;
        if (!FUSED) Bp[i] = B1 + (size_t)(cb + row)*K + kq;
        else {
            const float* bb = (row < 64) ? B1 : B3;
            Bp[i] = bb + (size_t)(cb + (row & 63))*K + kq;
        }
    }
    uint32_t sA = s2u(As), sB = s2u(Bs);

    float acc1[2][NJ][4];
    float acc3[FUSED?2:1][NJ][4];
#pragma unroll
    for (int i = 0; i < 2; i++)
#pragma unroll
        for (int j = 0; j < NJ; j++)
#pragma unroll
            for (int q = 0; q < 4; q++) { acc1[i][j][q] = 0.f; if (FUSED) acc3[i][j][q] = 0.f; }

    auto load = [&](int c, int s){
#pragma unroll
        for (int i = 0; i < 4; i++) {
            int lin = t + i*128;
            int row = lin >> 3, kq = (lin & 7) << 2;
            cp16(sA + (uint32_t)(((s*64 + row)*LDS + kq)*4), Ap[i] + (size_t)c*32);
        }
#pragma unroll
        for (int i = 0; i < 8; i++) {
            int lin = t + i*128;
            int row = lin >> 3, kq = (lin & 7) << 2;
            cp16(sB + (uint32_t)(((s*128 + row)*LDS + kq)*4), Bp[i] + (size_t)c*32);
        }
        CP_COMMIT();
    };

    const int NC = K >> 5;
    load(0, 0);
    load(1, 1);
    for (int c = 0; c < NC; c++) {
        if (c+1 < NC) asm volatile("cp.async.wait_group 1;");
        else          asm volatile("cp.async.wait_group 0;");
        __syncthreads();
        if (c+2 < NC) load(c+2, (c+2)%3);
        int s = c % 3;
        const float* Ab = As + (size_t)s*64*LDS;
        const float* Bb = Bs + (size_t)s*128*LDS;
#pragma unroll
        for (int ks = 0; ks < 4; ks++) {
            int k0 = ks*8;
            uint32_t a[2][4];
#pragma unroll
            for (int i = 0; i < 2; i++) {
                int r0 = wr*32 + i*16;
                a[i][0] = fau(Ab[(r0+tq  )*LDS + k0+tr  ]);
                a[i][1] = fau(Ab[(r0+tq+8)*LDS + k0+tr  ]);
                a[i][2] = fau(Ab[(r0+tq  )*LDS + k0+tr+4]);
                a[i][3] = fau(Ab[(r0+tq+8)*LDS + k0+tr+4]);
            }
#pragma unroll
            for (int j = 0; j < NJ; j++) {
                int bc = wc*(NJ*8) + j*8 + tq;
                uint32_t b0 = fau(Bb[bc*LDS + k0+tr]);
                uint32_t b1 = fau(Bb[bc*LDS + k0+tr+4]);
#pragma unroll
                for (int i = 0; i < 2; i++) MMA8(acc1[i][j], a[i], b0, b1);
                if (FUSED) {
                    uint32_t c0 = fau(Bb[(bc+64)*LDS + k0+tr]);
                    uint32_t c1 = fau(Bb[(bc+64)*LDS + k0+tr+4]);
#pragma unroll
                    for (int i = 0; i < 2; i++) MMA8(acc3[i][j], a[i], c0, c1);
                }
            }
        }
    }

    // -------- epilogue --------
    if (MODE == 4) {
        // qkv GEMM with fused RoPE + head-split. Warp's 64 cols = one head of
        // q/k/v. Pair (d, d+32) sits in fragments j and j+4 of the same thread.
        int W0 = cb + wc*64;
        int region = W0 >> 9;                  // 0=q, 1=k, 2=v
        int head = (W0 & 511) >> 6;
        float* base = (region == 0) ? g_q : (region == 1) ? g_k : g_v;
#pragma unroll
        for (int i = 0; i < 2; i++)
#pragma unroll
            for (int hh = 0; hh < 2; hh++) {
                int gr = rb + wr*32 + i*16 + tq + hh*8;
                int b = gr >> 10, tt = gr & (Tt-1);
                float* dst = base + ((size_t)(b*NHh + head)*Tt + tt)*64;
#pragma unroll
                for (int j = 0; j < 4; j++) {
                    int d0 = j*8 + tr*2;
                    float v0 = acc1[i][j  ][hh*2], v1 = acc1[i][j  ][hh*2+1];
                    float u0 = acc1[i][j+4][hh*2], u1 = acc1[i][j+4][hh*2+1];
                    float2 lo, hi;
                    if (region == 2) {
                        lo.x = to_tf32(v0); lo.y = to_tf32(v1);
                        hi.x = to_tf32(u0); hi.y = to_tf32(u1);
                    } else {
                        float2 cs = *(const float2*)&g_cos[tt*32 + d0];
                        float2 sn = *(const float2*)&g_sin[tt*32 + d0];
                        float sc = (region == 0) ? 0.125f : 1.f;
                        lo.x = to_tf32((v0*cs.x - u0*sn.x)*sc);
                        lo.y = to_tf32((v1*cs.y - u1*sn.y)*sc);
                        hi.x = to_tf32((v0*sn.x + u0*cs.x)*sc);
                        hi.y = to_tf32((v1*sn.y + u1*cs.y)*sc);
                    }
                    *(float2*)(dst + d0)      = lo;
                    *(float2*)(dst + d0 + 32) = hi;
                }
            }
        return;
    }
#pragma unroll
    for (int i = 0; i < 2; i++)
#pragma unroll
        for (int hh = 0; hh < 2; hh++) {
            int gr = rb + wr*32 + i*16 + tq + hh*8;
            if (GROUPED && gr >= n) continue;
            int orow = gr; float wv = 1.f;
            if (GROUPED && MODE == 3) {
                int pk = tok[(size_t)e*NT + gr];
                wv   = wtv[(size_t)e*NT + gr];
                orow = pk >> 1;
            }
            float* cr = C + (size_t)orow*ldc;
#pragma unroll
            for (int j = 0; j < NJ; j++) {
                int gc = cb + wc*(NJ*8) + j*8 + tr*2;
                float v0 = acc1[i][j][hh*2], v1 = acc1[i][j][hh*2+1];
                if (FUSED) {
                    float u0 = acc3[i][j][hh*2], u1 = acc3[i][j][hh*2+1];
                    float2 o;
                    o.x = to_tf32(v0/(1.f+__expf(-v0))*u0);
                    o.y = to_tf32(v1/(1.f+__expf(-v1))*u1);
                    *(float2*)(cr + gc) = o;
                } else if (MODE == 0) {
                    float2 o = {v0, v1};
                    *(float2*)(cr + gc) = o;
                } else if (MODE == 1) {
                    float2 o = *(float2*)(cr + gc);
                    o.x += v0; o.y += v1;
                    *(float2*)(cr + gc) = o;
                } else {
                    atomicAdd(cr + gc,     wv*v0);
                    atomicAdd(cr + gc + 1, wv*v1);
                }
            }
        }
}

// ---------------- rope tables --------------------------------------------------
__global__ void rope_tables_kernel(){
    int idx = blockIdx.x*256 + threadIdx.x;
    if (idx >= Tt*32) return;
    int tt = idx >> 5, d = idx & 31;
    float inv = expf(-(float)d*0.28782313662425575f);
    float sn, cs; sincosf((float)tt*inv, &sn, &cs);
    g_cos[idx] = cs; g_sin[idx] = sn;
}

// ---------------- weight rounding fp32 -> RN tf32 ----------------------------
__global__ void round_copy(const float* __restrict__ s, float* __restrict__ d, int n4){
    int i = blockIdx.x*256 + threadIdx.x;
    if (i >= n4) return;
    float4 v = ((const float4*)s)[i];
    v.x=to_tf32(v.x); v.y=to_tf32(v.y); v.z=to_tf32(v.z); v.w=to_tf32(v.w);
    ((float4*)d)[i] = v;
}

// ---------------- rmsnorm ------------------------------------------------------
template<bool ROUND>
__global__ void rmsnorm_kernel(const float* __restrict__ in, const float* __restrict__ w,
                               float* __restrict__ out, float* __restrict__ out32){
    int row = blockIdx.x;
    const float* x = in + (size_t)row*Dd;
    float s = 0.f;
    for (int j = threadIdx.x; j < Dd; j += 256) { float v = x[j]; s += v*v; }
    __shared__ float red[8];
    for (int o = 16; o; o >>= 1) s += __shfl_xor_sync(0xffffffffu, s, o);
    if ((threadIdx.x & 31) == 0) red[threadIdx.x>>5] = s;
    __syncthreads();
    if (threadIdx.x < 8) {
        float v = red[threadIdx.x];
        for (int o = 4; o; o >>= 1) v += __shfl_xor_sync(0xffu, v, o);
        if (threadIdx.x == 0) red[0] = v;
    }
    __syncthreads();
    float rms = rsqrtf(red[0]/(float)Dd + 1e-5f);
    for (int j = threadIdx.x; j < Dd; j += 256) {
        float v = w[j]*x[j]*rms;
        out[(size_t)row*Dd+j] = ROUND ? to_tf32(v) : v;
        if (out32) out32[(size_t)row*Dd+j] = v;
    }
}

// ---------------- tensor-core flash attention (causal, HD=64) -----------------
#define LDP 72
__global__ void __launch_bounds__(128) attn_tc_kernel(
    const float* __restrict__ Q, const float* __restrict__ K,
    const float* __restrict__ V, float* __restrict__ Out)
{
    extern __shared__ float sm[];
    float* Ks = sm;
    float* Vs = sm + 2*64*LDP;
    float* Ps = sm + 4*64*LDP;
    int bh = blockIdx.y;
    int t = threadIdx.x, lane = t & 31, w = t >> 5;
    int tq = lane >> 2, tr = lane & 3;
    const float* Qb = Q + (size_t)bh*Tt*64;
    const float* Kb = K + (size_t)bh*Tt*64;
    const float* Vb = V + (size_t)bh*Tt*64;
    int b = bh >> 3, hh = bh & 7;
    uint32_t sK = s2u(Ks), sV = s2u(Vs);

    auto load_kv = [&](int kt, int buf){
        const float* ks = Kb + (size_t)kt*64*64;
        const float* vs = Vb + (size_t)kt*64*64;
        uint32_t kd = sK + buf*64*LDP*4;
        uint32_t vd = sV + buf*64*LDP*4;
#pragma unroll
        for (int i = 0; i < 8; i++) {
            int u = t + i*128;
            int row = u >> 4, seg = u & 15;
            uint32_t off = (uint32_t)((row*LDP + seg*4)*4);
            cp16(kd + off, ks + row*64 + seg*4);
            cp16(vd + off, vs + row*64 + seg*4);
        }
        CP_COMMIT();
    };

    for (int pass = 0; pass < 2; pass++) {
        int qt = pass ? (15 - (int)blockIdx.x) : (int)blockIdx.x;
        int nkt = qt + 1;
        __syncthreads();
        load_kv(0, 0);
        for (int u = t; u < 64*16; u += 128) {
            int row = u >> 4, seg = u & 15;
            *(float4*)&Ps[row*LDP + seg*4] = *(const float4*)(Qb + (size_t)(qt*64+row)*64 + seg*4);
        }
        __syncthreads();
        uint32_t qa[8][4];
        int r0 = w*16 + tq;
#pragma unroll
        for (int ks = 0; ks < 8; ks++) {
            qa[ks][0] = fau(Ps[ r0   *LDP + ks*8+tr  ]);
            qa[ks][1] = fau(Ps[(r0+8)*LDP + ks*8+tr  ]);
            qa[ks][2] = fau(Ps[ r0   *LDP + ks*8+tr+4]);
            qa[ks][3] = fau(Ps[(r0+8)*LDP + ks*8+tr+4]);
        }
        float o[8][4];
#pragma unroll
        for (int j = 0; j < 8; j++)
#pragma unroll
            for (int q = 0; q < 4; q++) o[j][q] = 0.f;
        float m0 = -1e30f, m1 = -1e30f, l0 = 0.f, l1 = 0.f;

        for (int kt = 0; kt < nkt; kt++) {
            int buf = kt & 1;
            __syncthreads();
            if (kt+1 < nkt) { load_kv(kt+1, buf^1); asm volatile("cp.async.wait_group 1;"); }
            else asm volatile("cp.async.wait_group 0;");
            __syncthreads();

            const float* Kt = Ks + buf*64*LDP;
            const float* Vt = Vs + buf*64*LDP;
            float s[8][4];
#pragma unroll
            for (int j = 0; j < 8; j++)
#pragma unroll
                for (int q = 0; q < 4; q++) s[j][q] = 0.f;
#pragma unroll
            for (int nf = 0; nf < 8; nf++) {
#pragma unroll
                for (int ks = 0; ks < 8; ks++) {
                    uint32_t b0 = fau(Kt[(nf*8+tq)*LDP + ks*8+tr  ]);
                    uint32_t b1 = fau(Kt[(nf*8+tq)*LDP + ks*8+tr+4]);
                    MMA8(s[nf], qa[ks], b0, b1);
                }
            }
            if (kt == qt) {
                int qr0 = qt*64 + r0, qr1 = qr0 + 8;
#pragma unroll
                for (int nf = 0; nf < 8; nf++) {
                    int kc = kt*64 + nf*8 + 2*tr;
                    if (kc   > qr0) s[nf][0] = -1e30f;
                    if (kc+1 > qr0) s[nf][1] = -1e30f;
                    if (kc   > qr1) s[nf][2] = -1e30f;
                    if (kc+1 > qr1) s[nf][3] = -1e30f;
                }
            }
            float rm0 = -1e30f, rm1 = -1e30f;
#pragma unroll
            for (int nf = 0; nf < 8; nf++) {
                rm0 = fmaxf(rm0, fmaxf(s[nf][0], s[nf][1]));
                rm1 = fmaxf(rm1, fmaxf(s[nf][2], s[nf][3]));
            }
            rm0 = fmaxf(rm0, __shfl_xor_sync(0xffffffffu, rm0, 1));
            rm0 = fmaxf(rm0, __shfl_xor_sync(0xffffffffu, rm0, 2));
            rm1 = fmaxf(rm1, __shfl_xor_sync(0xffffffffu, rm1, 1));
            rm1 = fmaxf(rm1, __shfl_xor_sync(0xffffffffu, rm1, 2));
            float nm0 = fmaxf(m0, rm0), nm1 = fmaxf(m1, rm1);
            float f0 = __expf(m0 - nm0), f1 = __expf(m1 - nm1);
            float rs0 = 0.f, rs1 = 0.f;
#pragma unroll
            for (int nf = 0; nf < 8; nf++) {
                float p0 = __expf(s[nf][0] - nm0);
                float p1 = __expf(s[nf][1] - nm0);
                float p2 = __expf(s[nf][2] - nm1);
                float p3 = __expf(s[nf][3] - nm1);
                rs0 += p0 + p1; rs1 += p2 + p3;
                Ps[ r0   *LDP + nf*8 + 2*tr    ] = to_tf32(p0);
                Ps[ r0   *LDP + nf*8 + 2*tr + 1] = to_tf32(p1);
                Ps[(r0+8)*LDP + nf*8 + 2*tr    ] = to_tf32(p2);
                Ps[(r0+8)*LDP + nf*8 + 2*tr + 1] = to_tf32(p3);
            }
            rs0 += __shfl_xor_sync(0xffffffffu, rs0, 1);
            rs0 += __shfl_xor_sync(0xffffffffu, rs0, 2);
            rs1 += __shfl_xor_sync(0xffffffffu, rs1, 1);
            rs1 += __shfl_xor_sync(0xffffffffu, rs1, 2);
            l0 = l0*f0 + rs0; m0 = nm0;
            l1 = l1*f1 + rs1; m1 = nm1;
#pragma unroll
            for (int j = 0; j < 8; j++) { o[j][0]*=f0; o[j][1]*=f0; o[j][2]*=f1; o[j][3]*=f1; }
            __syncwarp();
            uint32_t pa[8][4];
#pragma unroll
            for (int ks = 0; ks < 8; ks++) {
                pa[ks][0] = fau(Ps[ r0   *LDP + ks*8+tr  ]);
                pa[ks][1] = fau(Ps[(r0+8)*LDP + ks*8+tr  ]);
                pa[ks][2] = fau(Ps[ r0   *LDP + ks*8+tr+4]);
                pa[ks][3] = fau(Ps[(r0+8)*LDP + ks*8+tr+4]);
            }
#pragma unroll
            for (int nf = 0; nf < 8; nf++) {
#pragma unroll
                for (int ks = 0; ks < 8; ks++) {
                    uint32_t b0 = fau(Vt[(ks*8+tr  )*LDP + nf*8+tq]);
                    uint32_t b1 = fau(Vt[(ks*8+tr+4)*LDP + nf*8+tq]);
                    MMA8(o[nf], pa[ks], b0, b1);
                }
            }
        }
        float il0 = 1.f/l0, il1 = 1.f/l1;
        int qr = qt*64 + r0;
        float* o0 = Out + ((size_t)(b*Tt + qr    ))*Dd + hh*64;
        float* o1 = Out + ((size_t)(b*Tt + qr + 8))*Dd + hh*64;
#pragma unroll
        for (int nf = 0; nf < 8; nf++) {
            int gc = nf*8 + 2*tr;
            float2 a = { to_tf32(o[nf][0]*il0), to_tf32(o[nf][1]*il0) };
            float2 c = { to_tf32(o[nf][2]*il1), to_tf32(o[nf][3]*il1) };
            *(float2*)(o0 + gc) = a;
            *(float2*)(o1 + gc) = c;
        }
    }
}

// ---------------- router (fp32, unrounded input) ------------------------------
__global__ void router_kernel(const float* __restrict__ X, const float* __restrict__ RW,
                              int* __restrict__ cnt, int* __restrict__ tok, float* __restrict__ wt){
    int g = blockIdx.x*blockDim.x + threadIdx.x;
    int warp = g>>5, lane = g&31;
    if (warp >= NT) return;
    const float* xr = X + (size_t)warp*Dd;
    float lg[Ee];
#pragma unroll
    for (int e = 0; e < Ee; e++) {
        const float* w = RW + (size_t)e*Dd;
        float s = 0.f;
        for (int j = lane; j < Dd; j += 32) s += xr[j]*w[j];
        for (int o = 16; o; o >>= 1) s += __shfl_xor_sync(0xffffffffu, s, o);
        lg[e] = s;
    }
    if (lane == 0) {
        int i0 = 0; float v0 = lg[0];
#pragma unroll
        for (int e = 1; e < Ee; e++) if (lg[e] > v0) { v0 = lg[e]; i0 = e; }
        int i1 = -1; float v1 = -3.4e38f;
#pragma unroll
        for (int e = 0; e < Ee; e++) if (e != i0 && lg[e] > v1) { v1 = lg[e]; i1 = e; }
        float e1 = expf(v1 - v0);
        float w0 = 1.f/(1.f+e1), w1 = e1/(1.f+e1);
        int p0 = atomicAdd(&cnt[i0], 1);
        tok[i0*NT+p0] = warp*2;   wt[i0*NT+p0] = w0;
        int p1 = atomicAdd(&cnt[i1], 1);
        tok[i1*NT+p1] = warp*2+1; wt[i1*NT+p1] = w1;
    }
}

// ---------------- host orchestration ------------------------------------------
extern "C" void kernel_launch(void* const* d_in, const int* in_sizes, int n_in,
                              void* d_out, int out_size) {
    (void)in_sizes; (void)n_in; (void)out_size;
    const float* x        = (const float*)d_in[0];
    const float* qkv_w    = (const float*)d_in[1];
    const float* out_w    = (const float*)d_in[2];
    const float* norm1_w  = (const float*)d_in[3];
    const float* norm2_w  = (const float*)d_in[4];
    const float* router_w = (const float*)d_in[5];
    const float* moe_w1   = (const float*)d_in[6];
    const float* moe_w2   = (const float*)d_in[7];
    const float* moe_w3   = (const float*)d_in[8];
    const float* f_w1     = (const float*)d_in[9];
    const float* f_w2     = (const float*)d_in[10];
    const float* f_w3     = (const float*)d_in[11];
    const float* norm_f   = (const float*)d_in[12];
    float* out = (float*)d_out;

    float *h,*xn,*xn32,*q,*k,*v,*attn,*hbuf,*wt,*wr;
    int *cnt,*tok;
    cudaGetSymbolAddress((void**)&h, g_h);       cudaGetSymbolAddress((void**)&xn, g_xn);
    cudaGetSymbolAddress((void**)&xn32, g_xn32);
    cudaGetSymbolAddress((void**)&q, g_q);       cudaGetSymbolAddress((void**)&k, g_k);
    cudaGetSymbolAddress((void**)&v, g_v);       cudaGetSymbolAddress((void**)&attn, g_attn);
    cudaGetSymbolAddress((void**)&hbuf, g_hbuf);
    cudaGetSymbolAddress((void**)&wr, g_wr);     cudaGetSymbolAddress((void**)&cnt, g_cnt);
    cudaGetSymbolAddress((void**)&tok, g_tok);   cudaGetSymbolAddress((void**)&wt, g_wt);

    static cudaStream_t s1 = nullptr;
    static cudaEvent_t evF = nullptr, evJ0 = nullptr, evJ1 = nullptr, evJ2 = nullptr;
    if (!s1) {
        cudaStreamCreateWithFlags(&s1, cudaStreamNonBlocking);
        cudaEventCreateWithFlags(&evF,  cudaEventDisableTiming);
        cudaEventCreateWithFlags(&evJ0, cudaEventDisableTiming);
        cudaEventCreateWithFlags(&evJ1, cudaEventDisableTiming);
        cudaEventCreateWithFlags(&evJ2, cudaEventDisableTiming);
    }

    const int attn_smem = 5*64*LDP*sizeof(float);
    cudaFuncSetAttribute(attn_tc_kernel, cudaFuncAttributeMaxDynamicSharedMemorySize, attn_smem);
    const int SM3 = (3*64*36 + 3*128*36)*4;     // 82,944 B
    cudaFuncSetAttribute(mm_kernel<false,false,0>, cudaFuncAttributeMaxDynamicSharedMemorySize, SM3);
    cudaFuncSetAttribute(mm_kernel<false,false,1>, cudaFuncAttributeMaxDynamicSharedMemorySize, SM3);
    cudaFuncSetAttribute(mm_kernel<false,false,4>, cudaFuncAttributeMaxDynamicSharedMemorySize, SM3);
    cudaFuncSetAttribute(mm_kernel<false,true ,3>, cudaFuncAttributeMaxDynamicSharedMemorySize, SM3);
    cudaFuncSetAttribute(mm_kernel<true ,false,0>, cudaFuncAttributeMaxDynamicSharedMemorySize, SM3);
    cudaFuncSetAttribute(mm_kernel<true ,true ,0>, cudaFuncAttributeMaxDynamicSharedMemorySize, SM3);

    // ---- fork: big weight rounding on s1 -------------------------------------
    cudaEventRecord(evF, 0);
    cudaStreamWaitEvent(s1, evF, 0);
    #define RC(st, src, dstoff, nfl) \
        round_copy<<<(int)(((nfl)/4+255)/256),256,0,st>>>((src), wr+(dstoff), (int)((nfl)/4))
    RC(s1, moe_w1,            OFF_MW1,        SZ_MW1);
    RC(s1, moe_w3,            OFF_MW3,        SZ_MW1);
    RC(s1, moe_w2,            OFF_MW2,        SZ_MW1);
    cudaEventRecord(evJ0, s1);
    RC(s1, f_w1, OFF_FW1, SZ_FW);
    RC(s1, f_w3, OFF_FW3, SZ_FW);
    RC(s1, f_w2, OFF_FW2, SZ_FW);
    cudaEventRecord(evJ1, s1);
    RC(s1, moe_w1+SZ_MW1,     OFF_MW1+SZ_MW1, SZ_MW1);
    RC(s1, moe_w3+SZ_MW1,     OFF_MW3+SZ_MW1, SZ_MW1);
    RC(s1, moe_w2+SZ_MW1,     OFF_MW2+SZ_MW1, SZ_MW1);
    cudaEventRecord(evJ2, s1);

    // ---- main stream ---------------------------------------------------------
    rope_tables_kernel<<<(Tt*32+255)/256,256>>>();
    RC((cudaStream_t)0, qkv_w, OFF_QKV, SZ_QKV);
    RC((cudaStream_t)0, out_w, OFF_OUT, SZ_OUT);
    cudaMemcpyAsync(h, x, (size_t)NT*Dd*sizeof(float), cudaMemcpyDeviceToDevice, 0);

    for (int l = 0; l < Ll; l++) {
        rmsnorm_kernel<true><<<NT,256>>>(h, norm1_w+(size_t)l*Dd, xn, nullptr);
        mm_kernel<false,false,4><<<dim3(12,32),128,SM3>>>(
            xn, wr+OFF_QKV+(size_t)l*1536*Dd, nullptr, q /*unused*/,
            nullptr,nullptr,nullptr, Dd, 0, NT, 0,0,0);
        attn_tc_kernel<<<dim3(8, Bz*NHh),128,attn_smem>>>(q, k, v, attn);
        mm_kernel<false,false,1><<<dim3(4,32),128,SM3>>>(
            attn, wr+OFF_OUT+(size_t)l*Dd*Dd, nullptr, h,
            nullptr,nullptr,nullptr, Dd, Dd, NT, 0,0,0);

        if (l == 0 || l == 2) {
            int m = l/2;
            rmsnorm_kernel<true><<<NT,256>>>(h, norm2_w+(size_t)l*Dd, xn, xn32);
            cudaMemsetAsync(cnt, 0, Ee*sizeof(int), 0);
            router_kernel<<<(NT*32+127)/128,128>>>(xn32, router_w+(size_t)m*Ee*Dd, cnt, tok, wt);
            cudaStreamWaitEvent((cudaStream_t)0, m == 0 ? evJ0 : evJ2, 0);
            mm_kernel<true,true,0><<<dim3(Hh/64,32,Ee),128,SM3>>>(
                xn, wr+OFF_MW1+(size_t)m*SZ_MW1, wr+OFF_MW3+(size_t)m*SZ_MW1, hbuf,
                cnt, tok, nullptr, Dd, Hh, 0, 0, (long long)Hh*Dd, (long long)NT*Hh);
            mm_kernel<false,true,3><<<dim3(4,32,Ee),128,SM3>>>(
                hbuf, wr+OFF_MW2+(size_t)m*SZ_MW1, nullptr, h,
                cnt, tok, wt, Hh, Dd, 0, (long long)NT*Hh, (long long)Dd*Hh, 0);
        } else {
            int m = (l == 1) ? 0 : 1;
            rmsnorm_kernel<true><<<NT,256>>>(h, norm2_w+(size_t)l*Dd, xn, nullptr);
            if (l == 1) cudaStreamWaitEvent((cudaStream_t)0, evJ1, 0);
            mm_kernel<true,false,0><<<dim3(Hh/64,32),128,SM3>>>(
                xn, wr+OFF_FW1+(size_t)m*Hh*Dd, wr+OFF_FW3+(size_t)m*Hh*Dd, hbuf,
                nullptr,nullptr,nullptr, Dd, Hh, NT, 0,0,0);
            mm_kernel<false,false,1><<<dim3(4,32),128,SM3>>>(
                hbuf, wr+OFF_FW2+(size_t)m*Dd*Hh, nullptr, h,
                nullptr,nullptr,nullptr, Hh, Dd, NT, 0,0,0);
        }
    }
    rmsnorm_kernel<false><<<NT,256>>>(h, norm_f, out, nullptr);
}

// round 16
// speedup vs baseline: 1.1157x; 1.0248x over previous
#include <cuda_runtime.h>
#include <math.h>
#include <stdint.h>

#define Bz 2
#define Tt 1024
#define Dd 512
#define NHh 8
#define Ll 4
#define Ee 8
#define Hh 2048
#define NT (Bz*Tt)

#define SZ_QKV ((size_t)Ll*1536*Dd)
#define SZ_OUT ((size_t)Ll*Dd*Dd)
#define SZ_MW  ((size_t)2*Ee*Hh*Dd)
#define SZ_MW1 (SZ_MW/2)
#define SZ_FW  ((size_t)2*Hh*Dd)
#define OFF_QKV 0ull
#define OFF_OUT (OFF_QKV+SZ_QKV)
#define OFF_MW1 (OFF_OUT+SZ_OUT)
#define OFF_MW3 (OFF_MW1+SZ_MW)
#define OFF_MW2 (OFF_MW3+SZ_MW)
#define OFF_FW1 (OFF_MW2+SZ_MW)
#define OFF_FW3 (OFF_FW1+SZ_FW)
#define OFF_FW2 (OFF_FW3+SZ_FW)
#define WR_TOTAL (OFF_FW2+SZ_FW)

__device__ float g_h[NT*Dd];
__device__ float g_xn[NT*Dd];
__device__ float g_q[NT*Dd];
__device__ float g_k[NT*Dd];
__device__ float g_v[NT*Dd];
__device__ float g_attn[NT*Dd];
__device__ float g_hbuf[(size_t)Ee*NT*Hh];
__device__ float g_wr[WR_TOTAL];
__device__ float g_cos[Tt*32];
__device__ float g_sin[Tt*32];
__device__ int   g_cnt[Ee];
__device__ int   g_tok[Ee*NT];
__device__ float g_wt[Ee*NT];

// ---------------- helpers -----------------------------------------------------
__device__ __forceinline__ uint32_t s2u(const void* p){
    uint32_t a;
    asm("{ .reg .u64 t; cvta.to.shared.u64 t, %1; cvt.u32.u64 %0, t; }":"=r"(a):"l"(p));
    return a;
}
__device__ __forceinline__ float to_tf32(float x){
    uint32_t u; asm("cvt.rn.tf32.f32 %0, %1;":"=r"(u):"f"(x));
    return __uint_as_float(u);
}
__device__ __forceinline__ void cp16(uint32_t dst, const void* src){
    asm volatile("cp.async.cg.shared.global [%0], [%1], 16;"::"r"(dst),"l"(src));
}
#define CP_COMMIT() asm volatile("cp.async.commit_group;")
#define fau __float_as_uint

#define MMA8(d,a,b0,b1) \
  asm volatile("mma.sync.aligned.m16n8k8.row.col.f32.tf32.tf32.f32 " \
    "{%0,%1,%2,%3},{%4,%5,%6,%7},{%8,%9},{%0,%1,%2,%3};" \
    : "+f"((d)[0]),"+f"((d)[1]),"+f"((d)[2]),"+f"((d)[3]) \
    : "r"((a)[0]),"r"((a)[1]),"r"((a)[2]),"r"((a)[3]),"r"(b0),"r"(b1))

// ============ tf32 mma.sync GEMM v6: C = A @ B^T ==============================
// CTA: 128 threads (4 warps, 2x2). CTA tile 64 rows x (FUSED?64:128) cols.
// Warp tile 32 x 64 (non-fused) / 32 x 32 dual (fused).
// K-chunk 32, stride 36, 4-stage cp.async pipeline, up to TWO outstanding
// groups (wait_group 2 steady; tail waits 1 then 0 — exact pending count:
// min(c+3,NC)-1-c). ONE barrier per chunk.
// MODE 0 store, 1 +=, 3 weighted atomic scatter-add, 4 fused RoPE qkv-split.
template<bool FUSED, bool GROUPED, int MODE>
__global__ void __launch_bounds__(128) mm_kernel(
    const float* __restrict__ A, const float* __restrict__ B1, const float* __restrict__ B3,
    float* __restrict__ C, const int* __restrict__ cnt, const int* __restrict__ tok,
    const float* __restrict__ wtv, int K, int ldc, int nrows,
    long long sAe, long long sBe, long long sCe)
{
    constexpr int NCOLS = FUSED ? 64 : 128;
    constexpr int NJ    = NCOLS/16;            // n-frags per warp (8 or 4)
    constexpr int LDS   = 36;
    extern __shared__ float sm[];
    float* As = sm;                            // [4][64][36]
    float* Bs = sm + 4*64*LDS;                 // [4][128][36]

    int e = GROUPED ? blockIdx.z : 0;
    int n = GROUPED ? cnt[e] : nrows;
    int rb = blockIdx.y*64;
    if (rb >= n) return;
    int cb = blockIdx.x*NCOLS;
    if (GROUPED) {
        if (!FUSED) A += (size_t)e*sAe;
        B1 += (size_t)e*sBe;
        if (FUSED) B3 += (size_t)e*sBe;
        C += (size_t)e*sCe;
    }
    int t = threadIdx.x;
    int lane = t & 31, w = t >> 5;
    int wr = w >> 1, wc = w & 1;               // 2x2 warp grid
    int tq = lane >> 2, tr = lane & 3;

    const float* Ap[4]; const float* Bp[8];
#pragma unroll
    for (int i = 0; i < 4; i++) {
        int lin = t + i*128;
        int row = lin >> 3, kq = (lin & 7) << 2;
        int ar = rb + row; if (GROUPED && ar > n-1) ar = n-1;
        if (GROUPED && FUSED) Ap[i] = A + (size_t)(tok[(size_t)e*NT + ar] >> 1)*K + kq;
        else                  Ap[i] = A + (size_t)ar*K + kq;
    }
#pragma unroll
    for (int i = 0; i < 8; i++) {
        int lin = t + i*128;
        int row = lin >> 3, kq = (lin & 7) << 2;
        if (!FUSED) Bp[i] = B1 + (size_t)(cb + row)*K + kq;
        else {
            const float* bb = (row < 64) ? B1 : B3;
            Bp[i] = bb + (size_t)(cb + (row & 63))*K + kq;
        }
    }
    uint32_t sA = s2u(As), sB = s2u(Bs);

    float acc1[2][NJ][4];
    float acc3[FUSED?2:1][NJ][4];
#pragma unroll
    for (int i = 0; i < 2; i++)
#pragma unroll
        for (int j = 0; j < NJ; j++)
#pragma unroll
            for (int q = 0; q < 4; q++) { acc1[i][j][q] = 0.f; if (FUSED) acc3[i][j][q] = 0.f; }

    auto load = [&](int c, int s){
#pragma unroll
        for (int i = 0; i < 4; i++) {
            int lin = t + i*128;
            int row = lin >> 3, kq = (lin & 7) << 2;
            cp16(sA + (uint32_t)(((s*64 + row)*LDS + kq)*4), Ap[i] + (size_t)c*32);
        }
#pragma unroll
        for (int i = 0; i < 8; i++) {
            int lin = t + i*128;
            int row = lin >> 3, kq = (lin & 7) << 2;
            cp16(sB + (uint32_t)(((s*128 + row)*LDS + kq)*4), Bp[i] + (size_t)c*32);
        }
        CP_COMMIT();
    };

    const int NC = K >> 5;                      // >= 16 always here
    load(0, 0);
    load(1, 1);
    load(2, 2);
    for (int c = 0; c < NC; c++) {
        // pending groups newer than c: min(c+3,NC)-1-c  ->  2 / 1 / 0
        if      (c < NC-2) asm volatile("cp.async.wait_group 2;");
        else if (c < NC-1) asm volatile("cp.async.wait_group 1;");
        else               asm volatile("cp.async.wait_group 0;");
        __syncthreads();                        // chunk-c visible; compute(c-1) done before load(c+3) overwrite
        if (c+3 < NC) load(c+3, (c+3)&3);
        int s = c & 3;
        const float* Ab = As + (size_t)s*64*LDS;
        const float* Bb = Bs + (size_t)s*128*LDS;
#pragma unroll
        for (int ks = 0; ks < 4; ks++) {
            int k0 = ks*8;
            uint32_t a[2][4];
#pragma unroll
            for (int i = 0; i < 2; i++) {
                int r0 = wr*32 + i*16;
                a[i][0] = fau(Ab[(r0+tq  )*LDS + k0+tr  ]);
                a[i][1] = fau(Ab[(r0+tq+8)*LDS + k0+tr  ]);
                a[i][2] = fau(Ab[(r0+tq  )*LDS + k0+tr+4]);
                a[i][3] = fau(Ab[(r0+tq+8)*LDS + k0+tr+4]);
            }
#pragma unroll
            for (int j = 0; j < NJ; j++) {
                int bc = wc*(NJ*8) + j*8 + tq;
                uint32_t b0 = fau(Bb[bc*LDS + k0+tr]);
                uint32_t b1 = fau(Bb[bc*LDS + k0+tr+4]);
#pragma unroll
                for (int i = 0; i < 2; i++) MMA8(acc1[i][j], a[i], b0, b1);
                if (FUSED) {
                    uint32_t c0 = fau(Bb[(bc+64)*LDS + k0+tr]);
                    uint32_t c1 = fau(Bb[(bc+64)*LDS + k0+tr+4]);
#pragma unroll
                    for (int i = 0; i < 2; i++) MMA8(acc3[i][j], a[i], c0, c1);
                }
            }
        }
    }

    // -------- epilogue --------
    if (MODE == 4) {
        int W0 = cb + wc*64;
        int region = W0 >> 9;                  // 0=q, 1=k, 2=v
        int head = (W0 & 511) >> 6;
        float* base = (region == 0) ? g_q : (region == 1) ? g_k : g_v;
#pragma unroll
        for (int i = 0; i < 2; i++)
#pragma unroll
            for (int hh = 0; hh < 2; hh++) {
                int gr = rb + wr*32 + i*16 + tq + hh*8;
                int b = gr >> 10, tt = gr & (Tt-1);
                float* dst = base + ((size_t)(b*NHh + head)*Tt + tt)*64;
#pragma unroll
                for (int j = 0; j < 4; j++) {
                    int d0 = j*8 + tr*2;
                    float v0 = acc1[i][j  ][hh*2], v1 = acc1[i][j  ][hh*2+1];
                    float u0 = acc1[i][j+4][hh*2], u1 = acc1[i][j+4][hh*2+1];
                    float2 lo, hi;
                    if (region == 2) {
                        lo.x = to_tf32(v0); lo.y = to_tf32(v1);
                        hi.x = to_tf32(u0); hi.y = to_tf32(u1);
                    } else {
                        float2 cs = *(const float2*)&g_cos[tt*32 + d0];
                        float2 sn = *(const float2*)&g_sin[tt*32 + d0];
                        float sc = (region == 0) ? 0.125f : 1.f;
                        lo.x = to_tf32((v0*cs.x - u0*sn.x)*sc);
                        lo.y = to_tf32((v1*cs.y - u1*sn.y)*sc);
                        hi.x = to_tf32((v0*sn.x + u0*cs.x)*sc);
                        hi.y = to_tf32((v1*sn.y + u1*cs.y)*sc);
                    }
                    *(float2*)(dst + d0)      = lo;
                    *(float2*)(dst + d0 + 32) = hi;
                }
            }
        return;
    }
#pragma unroll
    for (int i = 0; i < 2; i++)
#pragma unroll
        for (int hh = 0; hh < 2; hh++) {
            int gr = rb + wr*32 + i*16 + tq + hh*8;
            if (GROUPED && gr >= n) continue;
            int orow = gr; float wv = 1.f;
            if (GROUPED && MODE == 3) {
                int pk = tok[(size_t)e*NT + gr];
                wv   = wtv[(size_t)e*NT + gr];
                orow = pk >> 1;
            }
            float* cr = C + (size_t)orow*ldc;
#pragma unroll
            for (int j = 0; j < NJ; j++) {
                int gc = cb + wc*(NJ*8) + j*8 + tr*2;
                float v0 = acc1[i][j][hh*2], v1 = acc1[i][j][hh*2+1];
                if (FUSED) {
                    float u0 = acc3[i][j][hh*2], u1 = acc3[i][j][hh*2+1];
                    float2 o;
                    o.x = to_tf32(v0/(1.f+__expf(-v0))*u0);
                    o.y = to_tf32(v1/(1.f+__expf(-v1))*u1);
                    *(float2*)(cr + gc) = o;
                } else if (MODE == 0) {
                    float2 o = {v0, v1};
                    *(float2*)(cr + gc) = o;
                } else if (MODE == 1) {
                    float2 o = *(float2*)(cr + gc);
                    o.x += v0; o.y += v1;
                    *(float2*)(cr + gc) = o;
                } else {
                    atomicAdd(cr + gc,     wv*v0);
                    atomicAdd(cr + gc + 1, wv*v1);
                }
            }
        }
}

// ---------------- rope tables --------------------------------------------------
__global__ void rope_tables_kernel(){
    int idx = blockIdx.x*256 + threadIdx.x;
    if (idx >= Tt*32) return;
    int tt = idx >> 5, d = idx & 31;
    float inv = expf(-(float)d*0.28782313662425575f);
    float sn, cs; sincosf((float)tt*inv, &sn, &cs);
    g_cos[idx] = cs; g_sin[idx] = sn;
}

// ---------------- weight rounding fp32 -> RN tf32 ----------------------------
__global__ void round_copy(const float* __restrict__ s, float* __restrict__ d, int n4){
    int i = blockIdx.x*256 + threadIdx.x;
    if (i >= n4) return;
    float4 v = ((const float4*)s)[i];
    v.x=to_tf32(v.x); v.y=to_tf32(v.y); v.z=to_tf32(v.z); v.w=to_tf32(v.w);
    ((float4*)d)[i] = v;
}

// ---------------- rmsnorm (+ optional fused MoE router) -----------------------
// 256 threads, 2 elems/thread (Dd=512). ROUTE: computes 8 expert logits from
// the UNROUNDED normed row (same values the old router read from xn32) and
// does top-2 + softmax + scatter in-block.
template<bool ROUND, bool ROUTE>
__global__ void rmsnorm_kernel(const float* __restrict__ in, const float* __restrict__ w,
                               float* __restrict__ out, const float* __restrict__ RW,
                               int* __restrict__ cnt, int* __restrict__ tok,
                               float* __restrict__ wt){
    int row = blockIdx.x;
    const float* x = in + (size_t)row*Dd;
    int t0 = threadIdx.x, t1 = threadIdx.x + 256;
    float x0 = x[t0], x1 = x[t1];
    float s = x0*x0 + x1*x1;
    __shared__ float red[8];
    for (int o = 16; o; o >>= 1) s += __shfl_xor_sync(0xffffffffu, s, o);
    if ((threadIdx.x & 31) == 0) red[threadIdx.x>>5] = s;
    __syncthreads();
    if (threadIdx.x < 8) {
        float v = red[threadIdx.x];
        for (int o = 4; o; o >>= 1) v += __shfl_xor_sync(0xffu, v, o);
        if (threadIdx.x == 0) red[0] = v;
    }
    __syncthreads();
    float rms = rsqrtf(red[0]/(float)Dd + 1e-5f);
    float v0 = w[t0]*x0*rms, v1 = w[t1]*x1*rms;
    out[(size_t)row*Dd+t0] = ROUND ? to_tf32(v0) : v0;
    out[(size_t)row*Dd+t1] = ROUND ? to_tf32(v1) : v1;
    if (ROUTE) {
        __shared__ float red2[8][8];
        float lg[Ee];
#pragma unroll
        for (int e = 0; e < Ee; e++) {
            float p = v0*RW[(size_t)e*Dd+t0] + v1*RW[(size_t)e*Dd+t1];
            for (int o = 16; o; o >>= 1) p += __shfl_xor_sync(0xffffffffu, p, o);
            lg[e] = p;
        }
        if ((threadIdx.x & 31) == 0) {
            int wp = threadIdx.x >> 5;
#pragma unroll
            for (int e = 0; e < Ee; e++) red2[wp][e] = lg[e];
        }
        __syncthreads();
        if (threadIdx.x == 0) {
            float L[Ee];
#pragma unroll
            for (int e = 0; e < Ee; e++) {
                float sum = 0.f;
#pragma unroll
                for (int wp = 0; wp < 8; wp++) sum += red2[wp][e];
                L[e] = sum;
            }
            int i0 = 0; float b0 = L[0];
#pragma unroll
            for (int e = 1; e < Ee; e++) if (L[e] > b0) { b0 = L[e]; i0 = e; }
            int i1 = -1; float b1 = -3.4e38f;
#pragma unroll
            for (int e = 0; e < Ee; e++) if (e != i0 && L[e] > b1) { b1 = L[e]; i1 = e; }
            float e1 = expf(b1 - b0);
            float w0 = 1.f/(1.f+e1), w1 = e1/(1.f+e1);
            int p0 = atomicAdd(&cnt[i0], 1);
            tok[i0*NT+p0] = row*2;   wt[i0*NT+p0] = w0;
            int p1 = atomicAdd(&cnt[i1], 1);
            tok[i1*NT+p1] = row*2+1; wt[i1*NT+p1] = w1;
        }
    }
}

// ---------------- tensor-core flash attention (causal, HD=64) -----------------
#define LDP 72
__global__ void __launch_bounds__(128) attn_tc_kernel(
    const float* __restrict__ Q, const float* __restrict__ K,
    const float* __restrict__ V, float* __restrict__ Out)
{
    extern __shared__ float sm[];
    float* Ks = sm;
    float* Vs = sm + 2*64*LDP;
    float* Ps = sm + 4*64*LDP;
    int bh = blockIdx.y;
    int t = threadIdx.x, lane = t & 31, w = t >> 5;
    int tq = lane >> 2, tr = lane & 3;
    const float* Qb = Q + (size_t)bh*Tt*64;
    const float* Kb = K + (size_t)bh*Tt*64;
    const float* Vb = V + (size_t)bh*Tt*64;
    int b = bh >> 3, hh = bh & 7;
    uint32_t sK = s2u(Ks), sV = s2u(Vs);

    auto load_kv = [&](int kt, int buf){
        const float* ks = Kb + (size_t)kt*64*64;
        const float* vs = Vb + (size_t)kt*64*64;
        uint32_t kd = sK + buf*64*LDP*4;
        uint32_t vd = sV + buf*64*LDP*4;
#pragma unroll
        for (int i = 0; i < 8; i++) {
            int u = t + i*128;
            int row = u >> 4, seg = u & 15;
            uint32_t off = (uint32_t)((row*LDP + seg*4)*4);
            cp16(kd + off, ks + row*64 + seg*4);
            cp16(vd + off, vs + row*64 + seg*4);
        }
        CP_COMMIT();
    };

    for (int pass = 0; pass < 2; pass++) {
        int qt = pass ? (15 - (int)blockIdx.x) : (int)blockIdx.x;
        int nkt = qt + 1;
        __syncthreads();
        load_kv(0, 0);
        for (int u = t; u < 64*16; u += 128) {
            int row = u >> 4, seg = u & 15;
            *(float4*)&Ps[row*LDP + seg*4] = *(const float4*)(Qb + (size_t)(qt*64+row)*64 + seg*4);
        }
        __syncthreads();
        uint32_t qa[8][4];
        int r0 = w*16 + tq;
#pragma unroll
        for (int ks = 0; ks < 8; ks++) {
            qa[ks][0] = fau(Ps[ r0   *LDP + ks*8+tr  ]);
            qa[ks][1] = fau(Ps[(r0+8)*LDP + ks*8+tr  ]);
            qa[ks][2] = fau(Ps[ r0   *LDP + ks*8+tr+4]);
            qa[ks][3] = fau(Ps[(r0+8)*LDP + ks*8+tr+4]);
        }
        float o[8][4];
#pragma unroll
        for (int j = 0; j < 8; j++)
#pragma unroll
            for (int q = 0; q < 4; q++) o[j][q] = 0.f;
        float m0 = -1e30f, m1 = -1e30f, l0 = 0.f, l1 = 0.f;

        for (int kt = 0; kt < nkt; kt++) {
            int buf = kt & 1;
            __syncthreads();
            if (kt+1 < nkt) { load_kv(kt+1, buf^1); asm volatile("cp.async.wait_group 1;"); }
            else asm volatile("cp.async.wait_group 0;");
            __syncthreads();

            const float* Kt = Ks + buf*64*LDP;
            const float* Vt = Vs + buf*64*LDP;
            float s[8][4];
#pragma unroll
            for (int j = 0; j < 8; j++)
#pragma unroll
                for (int q = 0; q < 4; q++) s[j][q] = 0.f;
#pragma unroll
            for (int nf = 0; nf < 8; nf++) {
#pragma unroll
                for (int ks = 0; ks < 8; ks++) {
                    uint32_t b0 = fau(Kt[(nf*8+tq)*LDP + ks*8+tr  ]);
                    uint32_t b1 = fau(Kt[(nf*8+tq)*LDP + ks*8+tr+4]);
                    MMA8(s[nf], qa[ks], b0, b1);
                }
            }
            if (kt == qt) {
                int qr0 = qt*64 + r0, qr1 = qr0 + 8;
#pragma unroll
                for (int nf = 0; nf < 8; nf++) {
                    int kc = kt*64 + nf*8 + 2*tr;
                    if (kc   > qr0) s[nf][0] = -1e30f;
                    if (kc+1 > qr0) s[nf][1] = -1e30f;
                    if (kc   > qr1) s[nf][2] = -1e30f;
                    if (kc+1 > qr1) s[nf][3] = -1e30f;
                }
            }
            float rm0 = -1e30f, rm1 = -1e30f;
#pragma unroll
            for (int nf = 0; nf < 8; nf++) {
                rm0 = fmaxf(rm0, fmaxf(s[nf][0], s[nf][1]));
                rm1 = fmaxf(rm1, fmaxf(s[nf][2], s[nf][3]));
            }
            rm0 = fmaxf(rm0, __shfl_xor_sync(0xffffffffu, rm0, 1));
            rm0 = fmaxf(rm0, __shfl_xor_sync(0xffffffffu, rm0, 2));
            rm1 = fmaxf(rm1, __shfl_xor_sync(0xffffffffu, rm1, 1));
            rm1 = fmaxf(rm1, __shfl_xor_sync(0xffffffffu, rm1, 2));
            float nm0 = fmaxf(m0, rm0), nm1 = fmaxf(m1, rm1);
            float f0 = __expf(m0 - nm0), f1 = __expf(m1 - nm1);
            float rs0 = 0.f, rs1 = 0.f;
#pragma unroll
            for (int nf = 0; nf < 8; nf++) {
                float p0 = __expf(s[nf][0] - nm0);
                float p1 = __expf(s[nf][1] - nm0);
                float p2 = __expf(s[nf][2] - nm1);
                float p3 = __expf(s[nf][3] - nm1);
                rs0 += p0 + p1; rs1 += p2 + p3;
                Ps[ r0   *LDP + nf*8 + 2*tr    ] = to_tf32(p0);
                Ps[ r0   *LDP + nf*8 + 2*tr + 1] = to_tf32(p1);
                Ps[(r0+8)*LDP + nf*8 + 2*tr    ] = to_tf32(p2);
                Ps[(r0+8)*LDP + nf*8 + 2*tr + 1] = to_tf32(p3);
            }
            rs0 += __shfl_xor_sync(0xffffffffu, rs0, 1);
            rs0 += __shfl_xor_sync(0xffffffffu, rs0, 2);
            rs1 += __shfl_xor_sync(0xffffffffu, rs1, 1);
            rs1 += __shfl_xor_sync(0xffffffffu, rs1, 2);
            l0 = l0*f0 + rs0; m0 = nm0;
            l1 = l1*f1 + rs1; m1 = nm1;
#pragma unroll
            for (int j = 0; j < 8; j++) { o[j][0]*=f0; o[j][1]*=f0; o[j][2]*=f1; o[j][3]*=f1; }
            __syncwarp();
            uint32_t pa[8][4];
#pragma unroll
            for (int ks = 0; ks < 8; ks++) {
                pa[ks][0] = fau(Ps[ r0   *LDP + ks*8+tr  ]);
                pa[ks][1] = fau(Ps[(r0+8)*LDP + ks*8+tr  ]);
                pa[ks][2] = fau(Ps[ r0   *LDP + ks*8+tr+4]);
                pa[ks][3] = fau(Ps[(r0+8)*LDP + ks*8+tr+4]);
            }
#pragma unroll
            for (int nf = 0; nf < 8; nf++) {
#pragma unroll
                for (int ks = 0; ks < 8; ks++) {
                    uint32_t b0 = fau(Vt[(ks*8+tr  )*LDP + nf*8+tq]);
                    uint32_t b1 = fau(Vt[(ks*8+tr+4)*LDP + nf*8+tq]);
                    MMA8(o[nf], pa[ks], b0, b1);
                }
            }
        }
        float il0 = 1.f/l0, il1 = 1.f/l1;
        int qr = qt*64 + r0;
        float* o0 = Out + ((size_t)(b*Tt + qr    ))*Dd + hh*64;
        float* o1 = Out + ((size_t)(b*Tt + qr + 8))*Dd + hh*64;
#pragma unroll
        for (int nf = 0; nf < 8; nf++) {
            int gc = nf*8 + 2*tr;
            float2 a = { to_tf32(o[nf][0]*il0), to_tf32(o[nf][1]*il0) };
            float2 c = { to_tf32(o[nf][2]*il1), to_tf32(o[nf][3]*il1) };
            *(float2*)(o0 + gc) = a;
            *(float2*)(o1 + gc) = c;
        }
    }
}

// ---------------- host orchestration ------------------------------------------
extern "C" void kernel_launch(void* const* d_in, const int* in_sizes, int n_in,
                              void* d_out, int out_size) {
    (void)in_sizes; (void)n_in; (void)out_size;
    const float* x        = (const float*)d_in[0];
    const float* qkv_w    = (const float*)d_in[1];
    const float* out_w    = (const float*)d_in[2];
    const float* norm1_w  = (const float*)d_in[3];
    const float* norm2_w  = (const float*)d_in[4];
    const float* router_w = (const float*)d_in[5];
    const float* moe_w1   = (const float*)d_in[6];
    const float* moe_w2   = (const float*)d_in[7];
    const float* moe_w3   = (const float*)d_in[8];
    const float* f_w1     = (const float*)d_in[9];
    const float* f_w2     = (const float*)d_in[10];
    const float* f_w3     = (const float*)d_in[11];
    const float* norm_f   = (const float*)d_in[12];
    float* out = (float*)d_out;

    float *h,*xn,*q,*k,*v,*attn,*hbuf,*wt,*wr;
    int *cnt,*tok;
    cudaGetSymbolAddress((void**)&h, g_h);       cudaGetSymbolAddress((void**)&xn, g_xn);
    cudaGetSymbolAddress((void**)&q, g_q);       cudaGetSymbolAddress((void**)&k, g_k);
    cudaGetSymbolAddress((void**)&v, g_v);       cudaGetSymbolAddress((void**)&attn, g_attn);
    cudaGetSymbolAddress((void**)&hbuf, g_hbuf);
    cudaGetSymbolAddress((void**)&wr, g_wr);     cudaGetSymbolAddress((void**)&cnt, g_cnt);
    cudaGetSymbolAddress((void**)&tok, g_tok);   cudaGetSymbolAddress((void**)&wt, g_wt);

    static cudaStream_t s1 = nullptr;
    static cudaEvent_t evF = nullptr, evJ0 = nullptr, evJ1 = nullptr, evJ2 = nullptr;
    if (!s1) {
        cudaStreamCreateWithFlags(&s1, cudaStreamNonBlocking);
        cudaEventCreateWithFlags(&evF,  cudaEventDisableTiming);
        cudaEventCreateWithFlags(&evJ0, cudaEventDisableTiming);
        cudaEventCreateWithFlags(&evJ1, cudaEventDisableTiming);
        cudaEventCreateWithFlags(&evJ2, cudaEventDisableTiming);
    }

    const int attn_smem = 5*64*LDP*sizeof(float);
    cudaFuncSetAttribute(attn_tc_kernel, cudaFuncAttributeMaxDynamicSharedMemorySize, attn_smem);
    const int SM4 = (4*64*36 + 4*128*36)*4;     // 110,592 B
    cudaFuncSetAttribute(mm_kernel<false,false,0>, cudaFuncAttributeMaxDynamicSharedMemorySize, SM4);
    cudaFuncSetAttribute(mm_kernel<false,false,1>, cudaFuncAttributeMaxDynamicSharedMemorySize, SM4);
    cudaFuncSetAttribute(mm_kernel<false,false,4>, cudaFuncAttributeMaxDynamicSharedMemorySize, SM4);
    cudaFuncSetAttribute(mm_kernel<false,true ,3>, cudaFuncAttributeMaxDynamicSharedMemorySize, SM4);
    cudaFuncSetAttribute(mm_kernel<true ,false,0>, cudaFuncAttributeMaxDynamicSharedMemorySize, SM4);
    cudaFuncSetAttribute(mm_kernel<true ,true ,0>, cudaFuncAttributeMaxDynamicSharedMemorySize, SM4);

    // ---- fork: big weight rounding on s1 -------------------------------------
    cudaEventRecord(evF, 0);
    cudaStreamWaitEvent(s1, evF, 0);
    #define RC(st, src, dstoff, nfl) \
        round_copy<<<(int)(((nfl)/4+255)/256),256,0,st>>>((src), wr+(dstoff), (int)((nfl)/4))
    RC(s1, moe_w1,            OFF_MW1,        SZ_MW1);
    RC(s1, moe_w3,            OFF_MW3,        SZ_MW1);
    RC(s1, moe_w2,            OFF_MW2,        SZ_MW1);
    cudaEventRecord(evJ0, s1);
    RC(s1, f_w1, OFF_FW1, SZ_FW);
    RC(s1, f_w3, OFF_FW3, SZ_FW);
    RC(s1, f_w2, OFF_FW2, SZ_FW);
    cudaEventRecord(evJ1, s1);
    RC(s1, moe_w1+SZ_MW1,     OFF_MW1+SZ_MW1, SZ_MW1);
    RC(s1, moe_w3+SZ_MW1,     OFF_MW3+SZ_MW1, SZ_MW1);
    RC(s1, moe_w2+SZ_MW1,     OFF_MW2+SZ_MW1, SZ_MW1);
    cudaEventRecord(evJ2, s1);

    // ---- main stream ---------------------------------------------------------
    rope_tables_kernel<<<(Tt*32+255)/256,256>>>();
    RC((cudaStream_t)0, qkv_w, OFF_QKV, SZ_QKV);
    RC((cudaStream_t)0, out_w, OFF_OUT, SZ_OUT);
    cudaMemcpyAsync(h, x, (size_t)NT*Dd*sizeof(float), cudaMemcpyDeviceToDevice, 0);

    for (int l = 0; l < Ll; l++) {
        rmsnorm_kernel<true,false><<<NT,256>>>(h, norm1_w+(size_t)l*Dd, xn,
                                               nullptr, nullptr, nullptr, nullptr);
        mm_kernel<false,false,4><<<dim3(12,32),128,SM4>>>(
            xn, wr+OFF_QKV+(size_t)l*1536*Dd, nullptr, q /*unused*/,
            nullptr,nullptr,nullptr, Dd, 0, NT, 0,0,0);
        attn_tc_kernel<<<dim3(8, Bz*NHh),128,attn_smem>>>(q, k, v, attn);
        mm_kernel<false,false,1><<<dim3(4,32),128,SM4>>>(
            attn, wr+OFF_OUT+(size_t)l*Dd*Dd, nullptr, h,
            nullptr,nullptr,nullptr, Dd, Dd, NT, 0,0,0);

        if (l == 0 || l == 2) {
            int m = l/2;
            cudaMemsetAsync(cnt, 0, Ee*sizeof(int), 0);
            rmsnorm_kernel<true,true><<<NT,256>>>(h, norm2_w+(size_t)l*Dd, xn,
                                                  router_w+(size_t)m*Ee*Dd, cnt, tok, wt);
            cudaStreamWaitEvent((cudaStream_t)0, m == 0 ? evJ0 : evJ2, 0);
            mm_kernel<true,true,0><<<dim3(Hh/64,32,Ee),128,SM4>>>(
                xn, wr+OFF_MW1+(size_t)m*SZ_MW1, wr+OFF_MW3+(size_t)m*SZ_MW1, hbuf,
                cnt, tok, nullptr, Dd, Hh, 0, 0, (long long)Hh*Dd, (long long)NT*Hh);
            mm_kernel<false,true,3><<<dim3(4,32,Ee),128,SM4>>>(
                hbuf, wr+OFF_MW2+(size_t)m*SZ_MW1, nullptr, h,
                cnt, tok, wt, Hh, Dd, 0, (long long)NT*Hh, (long long)Dd*Hh, 0);
        } else {
            int m = (l == 1) ? 0 : 1;
            rmsnorm_kernel<true,false><<<NT,256>>>(h, norm2_w+(size_t)l*Dd, xn,
                                                   nullptr, nullptr, nullptr, nullptr);
            if (l == 1) cudaStreamWaitEvent((cudaStream_t)0, evJ1, 0);
            mm_kernel<true,false,0><<<dim3(Hh/64,32),128,SM4>>>(
                xn, wr+OFF_FW1+(size_t)m*Hh*Dd, wr+OFF_FW3+(size_t)m*Hh*Dd, hbuf,
                nullptr,nullptr,nullptr, Dd, Hh, NT, 0,0,0);
            mm_kernel<false,false,1><<<dim3(4,32),128,SM4>>>(
                hbuf, wr+OFF_FW2+(size_t)m*Dd*Hh, nullptr, h,
                nullptr,nullptr,nullptr, Hh, Dd, NT, 0,0,0);
        }
    }
    rmsnorm_kernel<false,false><<<NT,256>>>(h, norm_f, out,
                                            nullptr, nullptr, nullptr, nullptr);
}